// round 13
// baseline (speedup 1.0000x reference)
#include <cuda_runtime.h>
#include <cuda_fp16.h>

#define N_NODES 50000
#define N_EDGES 625000
#define HID 128
#define KAN_HID 64
#define NB 9            /* 8 spline bases + silu as 9th */
#define K1 (HID*NB)     /* 1152 */
#define K1W (K1/2)      /* 576 packed words per phi row */
#define NBLK 196        /* ceil(N_NODES/256) */

typedef unsigned int u32;

/* ------------------------------------------------------------------ */
/* scratch (device globals; no allocations allowed)                    */
/* ------------------------------------------------------------------ */
__device__ int   g_is64_nz;           /* static zero-init; monotone 0->1 */
__device__ int   g_src[N_EDGES];
__device__ int   g_dst[N_EDGES];
__device__ int   g_ssrc[N_EDGES];
__device__ int   g_cnt[N_NODES];
__device__ int   g_off[N_NODES + 1];
__device__ int   g_cur[N_NODES];
__device__ int   g_bsum[256];
__device__ int   g_boff[256];
__device__ float g_h1[N_NODES * HID];
/* packed fp16 (2 per u32); A-side split hi/lo, B-side hi only         */
__device__ __align__(16) u32 g_aggh[N_NODES * 64], g_aggl[N_NODES * 64];
__device__ __align__(16) u32 g_xh[N_NODES * 64],   g_xl[N_NODES * 64];
__device__ __align__(16) u32 g_h1h[N_NODES * 64],  g_h1l[N_NODES * 64];
__device__ __align__(16) u32 g_phih[(size_t)N_NODES * K1W], g_phil[(size_t)N_NODES * K1W];
__device__ __align__(16) u32 g_w1h[HID * HID];   /* [c][128 words of k] */
__device__ __align__(16) u32 g_w2h[HID * HID];
__device__ __align__(16) u32 g_wch[KAN_HID * K1W];

/* grid value, matching jax: arange(-3, 9)*0.4 - 1 */
#define GRIDV(j) (0.4f * (float)((j) - 3) - 1.0f)

__device__ __forceinline__ void bspline_basis(float x, float* b /*[8]*/) {
    float t[11];
#pragma unroll
    for (int i = 0; i < 11; i++) {
        float g0 = GRIDV(i), g1 = GRIDV(i + 1);
        t[i] = (x >= g0 && x < g1) ? 1.0f : 0.0f;
    }
#pragma unroll
    for (int k = 1; k <= 3; k++) {
#pragma unroll
        for (int i = 0; i < 11; i++) {
            if (i < 11 - k) {
                float gi = GRIDV(i), gi1 = GRIDV(i + 1);
                float gik = GRIDV(i + k), gik1 = GRIDV(i + k + 1);
                t[i] = (x - gi) * (1.0f / (gik - gi)) * t[i]
                     + (gik1 - x) * (1.0f / (gik1 - gi1)) * t[i + 1];
            }
        }
    }
#pragma unroll
    for (int i = 0; i < 8; i++) b[i] = t[i];
}

__device__ __forceinline__ float silu_f(float x) {
    return x * (1.0f / (1.0f + __expf(-x)));
}

__device__ __forceinline__ u32 pack2h(float a, float b) {
    __half2 t = __floats2half2_rn(a, b);
    return *reinterpret_cast<u32*>(&t);
}
__device__ __forceinline__ void split2(float a, float b, u32& hi, u32& lo) {
    __half ah = __float2half_rn(a), bh = __float2half_rn(b);
    float ar = a - __half2float(ah);
    float br = b - __half2float(bh);
    __half2 h; h.x = ah; h.y = bh;
    hi = *reinterpret_cast<u32*>(&h);
    lo = pack2h(ar, br);
}

__device__ __forceinline__ u32 s2u(const void* p) {
    u32 a;
    asm("{ .reg .u64 t; cvta.to.shared.u64 t, %1; cvt.u32.u64 %0, t; }"
        : "=r"(a) : "l"(p));
    return a;
}

#define MMA16816(d, a, b0, b1)                                              \
    asm volatile("mma.sync.aligned.m16n8k16.row.col.f32.f16.f16.f32 "       \
                 "{%0,%1,%2,%3}, {%4,%5,%6,%7}, {%8,%9}, {%0,%1,%2,%3};\n"  \
                 : "+f"((d)[0]), "+f"((d)[1]), "+f"((d)[2]), "+f"((d)[3])   \
                 : "r"((a)[0]), "r"((a)[1]), "r"((a)[2]), "r"((a)[3]),      \
                   "r"(b0), "r"(b1))

#define LDSM4(f, addr)                                                      \
    asm volatile("ldmatrix.sync.aligned.m8n8.x4.shared.b16 {%0,%1,%2,%3}, [%4];" \
                 : "=r"((f)[0]), "=r"((f)[1]), "=r"((f)[2]), "=r"((f)[3])   \
                 : "r"(addr))

#define CPA16(dst, src, sz)                                                 \
    asm volatile("cp.async.cg.shared.global [%0], [%1], 16, %2;"            \
                 :: "r"(dst), "l"(src), "r"(sz) : "memory")
#define CPC()  asm volatile("cp.async.commit_group;" ::: "memory")
#define CPW1() asm volatile("cp.async.wait_group 1;" ::: "memory")
#define CPW0() asm volatile("cp.async.wait_group 0;" ::: "memory")

/* ------------------------------------------------------------------ */
/* fused: init counters + int64 detect + all weight/x fp16 conversion  */
/* grid = 12500 x 256                                                  */
/* ------------------------------------------------------------------ */
__global__ void initA_kernel(const int* __restrict__ e,
                             const float* __restrict__ x,
                             const float* __restrict__ W1l, const float* __restrict__ W1r,
                             const float* __restrict__ W2l, const float* __restrict__ W2r,
                             const float* __restrict__ kb1, const float* __restrict__ ks1) {
    int t = blockIdx.x * blockDim.x + threadIdx.x;
    if (t < N_NODES) g_cnt[t] = 0;
    if (t < 2048 && e[2 * t + 1] != 0) atomicOr(&g_is64_nz, 1);
    if (t < N_NODES * 64) {
        float2 v = ((const float2*)x)[t];
        split2(v.x, v.y, g_xh[t], g_xl[t]);
    }
    if (t < HID * HID) {
        int c = t >> 7, w = t & 127;
        int k0 = 2 * w, k1 = k0 + 1;
        float v0 = (k0 < 128) ? W1l[c * 128 + k0] : W1r[c * 128 + k0 - 128];
        float v1 = (k1 < 128) ? W1l[c * 128 + k1] : W1r[c * 128 + k1 - 128];
        g_w1h[t] = pack2h(v0, v1);
        v0 = (k0 < 128) ? W2l[c * 128 + k0] : W2r[c * 128 + k0 - 128];
        v1 = (k1 < 128) ? W2l[c * 128 + k1] : W2r[c * 128 + k1 - 128];
        g_w2h[t] = pack2h(v0, v1);
    }
    if (t < KAN_HID * K1W) {
        int o = t / K1W, w = t % K1W;
        int k0 = 2 * w, k1 = k0 + 1;
        int i0 = k0 / NB, j0 = k0 % NB;
        int i1 = k1 / NB, j1 = k1 % NB;
        float v0 = (j0 < 8) ? ks1[((size_t)o * 128 + i0) * 8 + j0] : kb1[o * 128 + i0];
        float v1 = (j1 < 8) ? ks1[((size_t)o * 128 + i1) * 8 + j1] : kb1[o * 128 + i1];
        g_wch[t] = pack2h(v0, v1);
    }
}

/* convert + histogram fused (reads g_is64_nz from previous kernel)    */
__global__ void convert_kernel(const int* __restrict__ e) {
    int i = blockIdx.x * blockDim.x + threadIdx.x;
    if (i >= N_EDGES) return;
    int s, d;
    if (g_is64_nz == 0) {
        s = e[2 * i];
        d = e[2 * N_EDGES + 2 * i];
    } else {
        s = e[i];
        d = e[N_EDGES + i];
    }
    g_src[i] = s;
    g_dst[i] = d;
    atomicAdd(&g_cnt[d], 1);
}

__device__ __forceinline__ int warp_incl_scan(int v) {
#pragma unroll
    for (int d = 1; d < 32; d <<= 1) {
        int t = __shfl_up_sync(0xffffffffu, v, d);
        if ((threadIdx.x & 31) >= d) v += t;
    }
    return v;
}

/* parallel 3-phase exclusive scan of g_cnt -> g_off / g_cur */
__global__ void scan1_kernel() {          /* grid NBLK x 256 */
    __shared__ int sh[8];
    int i = blockIdx.x * 256 + threadIdx.x;
    int v = (i < N_NODES) ? g_cnt[i] : 0;
    int lane = threadIdx.x & 31, w = threadIdx.x >> 5;
    int s = v;
#pragma unroll
    for (int d = 16; d > 0; d >>= 1) s += __shfl_down_sync(0xffffffffu, s, d);
    if (lane == 0) sh[w] = s;
    __syncthreads();
    if (threadIdx.x == 0) {
        int t = 0;
#pragma unroll
        for (int k = 0; k < 8; k++) t += sh[k];
        g_bsum[blockIdx.x] = t;
    }
}

__global__ void scan2_kernel() {          /* 1 block x 256 */
    __shared__ int sv[256];
    int i = threadIdx.x;
    int v = (i < NBLK) ? g_bsum[i] : 0;
    sv[i] = v;
    __syncthreads();
#pragma unroll
    for (int d = 1; d < 256; d <<= 1) {
        int t = (i >= d) ? sv[i - d] : 0;
        __syncthreads();
        sv[i] += t;
        __syncthreads();
    }
    if (i < NBLK) g_boff[i] = sv[i] - v;   /* exclusive */
    if (i == NBLK - 1) g_off[N_NODES] = sv[i];
}

__global__ void scan3_kernel() {          /* grid NBLK x 256 */
    __shared__ int wsums[8];
    int i = blockIdx.x * 256 + threadIdx.x;
    int v = (i < N_NODES) ? g_cnt[i] : 0;
    int lane = threadIdx.x & 31, w = threadIdx.x >> 5;
    int inc = warp_incl_scan(v);
    if (lane == 31) wsums[w] = inc;
    __syncthreads();
    int woff = 0;
    for (int k = 0; k < w; k++) woff += wsums[k];
    int excl = g_boff[blockIdx.x] + woff + inc - v;
    if (i < N_NODES) { g_off[i] = excl; g_cur[i] = excl; }
}

__global__ void scatter_kernel() {
    int i = blockIdx.x * blockDim.x + threadIdx.x;
    if (i >= N_EDGES) return;
    int d = g_dst[i];
    int p = atomicAdd(&g_cur[d], 1);
    g_ssrc[p] = g_src[i];
}

/* ------------------------------------------------------------------ */
/* mean aggregation: one warp per node, CSR, MLP=4; emits fp16 hi/lo   */
/* ------------------------------------------------------------------ */
__global__ void agg_kernel(const float* __restrict__ xext, int use_h1) {
    int gw = (blockIdx.x * blockDim.x + threadIdx.x) >> 5;
    if (gw >= N_NODES) return;
    const float* __restrict__ src = use_h1 ? g_h1 : xext;
    int lane = threadIdx.x & 31;
    int e0 = g_off[gw], e1 = g_off[gw + 1];
    float ax = 0.f, ay = 0.f, az = 0.f, aw = 0.f;
    int e = e0;
    int e4 = e0 + ((e1 - e0) & ~3);
    for (; e < e4; e += 4) {
        int s0 = g_ssrc[e], s1 = g_ssrc[e + 1], s2 = g_ssrc[e + 2], s3 = g_ssrc[e + 3];
        float4 v0 = __ldg((const float4*)(src + (size_t)s0 * HID) + lane);
        float4 v1 = __ldg((const float4*)(src + (size_t)s1 * HID) + lane);
        float4 v2 = __ldg((const float4*)(src + (size_t)s2 * HID) + lane);
        float4 v3 = __ldg((const float4*)(src + (size_t)s3 * HID) + lane);
        ax += v0.x + v1.x + v2.x + v3.x;
        ay += v0.y + v1.y + v2.y + v3.y;
        az += v0.z + v1.z + v2.z + v3.z;
        aw += v0.w + v1.w + v2.w + v3.w;
    }
    for (; e < e1; e++) {
        int s = g_ssrc[e];
        float4 v = __ldg((const float4*)(src + (size_t)s * HID) + lane);
        ax += v.x; ay += v.y; az += v.z; aw += v.w;
    }
    int c = e1 - e0;
    float inv = (c > 0) ? (1.0f / (float)c) : 0.0f;
    ax *= inv; ay *= inv; az *= inv; aw *= inv;
    u32 h0, l0, h1v, l1v;
    split2(ax, ay, h0, l0);
    split2(az, aw, h1v, l1v);
    size_t w0 = (size_t)gw * 64 + lane * 2;
    g_aggh[w0] = h0; g_aggh[w0 + 1] = h1v;
    g_aggl[w0] = l0; g_aggl[w0 + 1] = l1v;
}

/* ------------------------------------------------------------------ */
/* conv GEMM (mma.sync fp16 2-pass + cp.async + ldmatrix)              */
/* BM=128 BN=128 BK=32, 2-stage pipeline, 8 warps 4m x 2n              */
/* layer 0: epilogue -> f32 h1 + fp16 h1h/h1l                          */
/* layer 1: epilogue -> FUSED PHI (bspline+silu -> phih/phil)          */
/* ------------------------------------------------------------------ */
__global__ __launch_bounds__(256, 1) void conv_mma2_kernel(const float* __restrict__ bias,
                                                           int layer) {
    extern __shared__ u32 sm[];
    const u32* __restrict__ Ah1 = g_aggh;
    const u32* __restrict__ Al1 = g_aggl;
    const u32* __restrict__ Ah2 = layer ? g_h1h : g_xh;
    const u32* __restrict__ Al2 = layer ? g_h1l : g_xl;
    const u32* __restrict__ Wh  = layer ? g_w2h : g_w1h;

    int tid = threadIdx.x, lane = tid & 31, wid = tid >> 5;
    int m0 = blockIdx.x * 128;
    u32 smb = s2u(sm);

    int lr = tid & 127;
    bool isA = tid < 128;
    int gmr = m0 + lr;
    int gmc = (gmr < N_NODES) ? gmr : 0;
    u32 sz = isA ? ((gmr < N_NODES) ? 16u : 0u) : 16u;
    u32 swl = (lr & 7) * 4;
    u32 dstb = smb + ((isA ? 0 : 4096) + lr * 32) * 4;

    int q = lane >> 3, rr = lane & 7;
    int mrow0 = (wid & 3) * 32, ncol0 = (wid >> 2) * 64;
    u32 offAh[2][2], offAl[2][2], offBh[4][2];
#pragma unroll
    for (int mt = 0; mt < 2; mt++)
#pragma unroll
        for (int kk = 0; kk < 2; kk++) {
            int row = mrow0 + mt * 16 + rr + (q & 1) * 8;
            u32 swz = (row & 7) * 4;
            offAh[mt][kk] = (row * 32 + ((kk * 8 + (q >> 1) * 4) ^ swz)) * 4;
            offAl[mt][kk] = (row * 32 + ((16 + kk * 8 + (q >> 1) * 4) ^ swz)) * 4;
        }
#pragma unroll
    for (int p = 0; p < 4; p++)
#pragma unroll
        for (int kk = 0; kk < 2; kk++) {
            int row = ncol0 + p * 16 + (q >> 1) * 8 + rr;
            u32 swz = (row & 7) * 4;
            offBh[p][kk] = (row * 32 + ((kk * 8 + (q & 1) * 4) ^ swz)) * 4;
        }

    float acc[2][8][4];
#pragma unroll
    for (int mt = 0; mt < 2; mt++)
#pragma unroll
        for (int nt = 0; nt < 8; nt++)
#pragma unroll
            for (int c = 0; c < 4; c++) acc[mt][nt][c] = 0.0f;

#define CONV_LOAD(s, buf) do {                                                   \
        u32 db = dstb + (buf) * 32768;                                           \
        if (isA) {                                                               \
            const u32 *srcH, *srcL;                                              \
            if ((s) < 4) { srcH = Ah1 + (size_t)gmc * 64 + (s) * 16;             \
                           srcL = Al1 + (size_t)gmc * 64 + (s) * 16; }           \
            else         { srcH = Ah2 + (size_t)gmc * 64 + ((s) - 4) * 16;       \
                           srcL = Al2 + (size_t)gmc * 64 + ((s) - 4) * 16; }     \
            _Pragma("unroll")                                                    \
            for (int c = 0; c < 4; c++) {                                        \
                CPA16(db + ((c * 4) ^ swl) * 4, srcH + c * 4, sz);               \
                CPA16(db + (((16 + c * 4)) ^ swl) * 4, srcL + c * 4, sz);        \
            }                                                                    \
        } else {                                                                 \
            const u32* srcH = Wh + (size_t)lr * 128 + (s) * 16;                  \
            _Pragma("unroll")                                                    \
            for (int c = 0; c < 4; c++)                                          \
                CPA16(db + ((c * 4) ^ swl) * 4, srcH + c * 4, sz);               \
        } } while (0)

    CONV_LOAD(0, 0); CPC();
#pragma unroll 1
    for (int s = 0; s < 8; s++) {
        int buf = s & 1;
        if (s < 7) { CONV_LOAD(s + 1, buf ^ 1); CPC(); CPW1(); }
        else CPW0();
        __syncthreads();
        u32 Ab = smb + buf * 32768, Bb = Ab + 16384;
#pragma unroll
        for (int kk = 0; kk < 2; kk++) {
            u32 ah[2][4], al[2][4], bh[8][2];
#pragma unroll
            for (int mt = 0; mt < 2; mt++) {
                LDSM4(ah[mt], Ab + offAh[mt][kk]);
                LDSM4(al[mt], Ab + offAl[mt][kk]);
            }
#pragma unroll
            for (int p = 0; p < 4; p++) {
                u32 f[4];
                LDSM4(f, Bb + offBh[p][kk]);
                bh[2 * p][0] = f[0]; bh[2 * p][1] = f[1];
                bh[2 * p + 1][0] = f[2]; bh[2 * p + 1][1] = f[3];
            }
#pragma unroll
            for (int nt = 0; nt < 8; nt++)
#pragma unroll
                for (int mt = 0; mt < 2; mt++) {
                    MMA16816(acc[mt][nt], ah[mt], bh[nt][0], bh[nt][1]);
                    MMA16816(acc[mt][nt], al[mt], bh[nt][0], bh[nt][1]);
                }
        }
        __syncthreads();
    }
#undef CONV_LOAD

    int grp = lane >> 2, tig = lane & 3;
    if (layer == 0) {
#pragma unroll
        for (int mt = 0; mt < 2; mt++)
#pragma unroll
            for (int nt = 0; nt < 8; nt++) {
                int col = ncol0 + nt * 8 + 2 * tig;
                float bx = __ldg(bias + col), by = __ldg(bias + col + 1);
                int r0 = m0 + mrow0 + mt * 16 + grp;
                if (r0 < N_NODES) {
                    float v0 = fmaxf(acc[mt][nt][0] + bx, 0.0f);
                    float v1 = fmaxf(acc[mt][nt][1] + by, 0.0f);
                    *(float2*)&g_h1[(size_t)r0 * 128 + col] = make_float2(v0, v1);
                    u32 h, l; split2(v0, v1, h, l);
                    g_h1h[(size_t)r0 * 64 + (col >> 1)] = h;
                    g_h1l[(size_t)r0 * 64 + (col >> 1)] = l;
                }
                int r1 = r0 + 8;
                if (r1 < N_NODES) {
                    float v0 = fmaxf(acc[mt][nt][2] + bx, 0.0f);
                    float v1 = fmaxf(acc[mt][nt][3] + by, 0.0f);
                    *(float2*)&g_h1[(size_t)r1 * 128 + col] = make_float2(v0, v1);
                    u32 h, l; split2(v0, v1, h, l);
                    g_h1h[(size_t)r1 * 64 + (col >> 1)] = h;
                    g_h1l[(size_t)r1 * 64 + (col >> 1)] = l;
                }
            }
    } else {
        /* fused phi: h2 values -> bspline/silu -> phih/phil directly */
#pragma unroll
        for (int mt = 0; mt < 2; mt++)
#pragma unroll
            for (int nt = 0; nt < 8; nt++) {
                int col = ncol0 + nt * 8 + 2 * tig;
                float bx = __ldg(bias + col), by = __ldg(bias + col + 1);
                int pair = col >> 1;
#pragma unroll
                for (int half = 0; half < 2; half++) {
                    int r = m0 + mrow0 + mt * 16 + grp + half * 8;
                    if (r < N_NODES) {
                        float v0 = fmaxf(acc[mt][nt][half * 2 + 0] + bx, 0.0f);
                        float v1 = fmaxf(acc[mt][nt][half * 2 + 1] + by, 0.0f);
                        float v[18];
                        bspline_basis(v0, v);      v[8]  = silu_f(v0);
                        bspline_basis(v1, v + 9);  v[17] = silu_f(v1);
                        u32* ph = g_phih + (size_t)r * K1W + pair * 9;
                        u32* pl = g_phil + (size_t)r * K1W + pair * 9;
#pragma unroll
                        for (int w = 0; w < 9; w++) {
                            u32 h, l;
                            split2(v[2 * w], v[2 * w + 1], h, l);
                            ph[w] = h; pl[w] = l;
                        }
                    }
                }
            }
    }
}

/* ------------------------------------------------------------------ */
/* KAN1 GEMM (mma.sync fp16 2-pass) + FUSED KAN2 epilogue -> out       */
/* BM=128 BN=64 BK=32, 36 stages, 8 warps 4m x 2n (warp 32x32)         */
/* ------------------------------------------------------------------ */
__global__ __launch_bounds__(256, 1) void kan1_mma2_kernel(const float* __restrict__ kb2,
                                                           const float* __restrict__ ks2,
                                                           float* __restrict__ out) {
    extern __shared__ u32 sm[];
    int tid = threadIdx.x, lane = tid & 31, wid = tid >> 5;
    int m0 = blockIdx.x * 128;
    u32 smb = s2u(sm);

    int lr = tid & 127;
    bool isA = tid < 128;
    bool isB = (tid >= 128) && (tid < 192);
    int gmr = m0 + lr;
    int gmc = (gmr < N_NODES) ? gmr : 0;
    u32 sz = isA ? ((gmr < N_NODES) ? 16u : 0u) : 16u;
    u32 swl = (lr & 7) * 4;
    u32 dstb = smb + ((isA ? 0 : 4096) + lr * 32) * 4;

    int q = lane >> 3, rr = lane & 7;
    int mrow0 = (wid & 3) * 32, ncol0 = (wid >> 2) * 32;
    u32 offAh[2][2], offAl[2][2], offBh[2][2];
#pragma unroll
    for (int mt = 0; mt < 2; mt++)
#pragma unroll
        for (int kk = 0; kk < 2; kk++) {
            int row = mrow0 + mt * 16 + rr + (q & 1) * 8;
            u32 swz = (row & 7) * 4;
            offAh[mt][kk] = (row * 32 + ((kk * 8 + (q >> 1) * 4) ^ swz)) * 4;
            offAl[mt][kk] = (row * 32 + ((16 + kk * 8 + (q >> 1) * 4) ^ swz)) * 4;
        }
#pragma unroll
    for (int p = 0; p < 2; p++)
#pragma unroll
        for (int kk = 0; kk < 2; kk++) {
            int row = ncol0 + p * 16 + (q >> 1) * 8 + rr;
            u32 swz = (row & 7) * 4;
            offBh[p][kk] = (row * 32 + ((kk * 8 + (q & 1) * 4) ^ swz)) * 4;
        }

    float acc[2][4][4];
#pragma unroll
    for (int mt = 0; mt < 2; mt++)
#pragma unroll
        for (int nt = 0; nt < 4; nt++)
#pragma unroll
            for (int c = 0; c < 4; c++) acc[mt][nt][c] = 0.0f;

#define KAN_LOAD(s, buf) do {                                                    \
        u32 db = dstb + (buf) * 24576;                                           \
        if (isA) {                                                               \
            const u32* srcH = g_phih + (size_t)gmc * K1W + (s) * 16;             \
            const u32* srcL = g_phil + (size_t)gmc * K1W + (s) * 16;             \
            _Pragma("unroll")                                                    \
            for (int c = 0; c < 4; c++) {                                        \
                CPA16(db + ((c * 4) ^ swl) * 4, srcH + c * 4, sz);               \
                CPA16(db + (((16 + c * 4)) ^ swl) * 4, srcL + c * 4, sz);        \
            }                                                                    \
        } else if (isB) {                                                        \
            const u32* srcH = g_wch + (size_t)lr * K1W + (s) * 16;               \
            _Pragma("unroll")                                                    \
            for (int c = 0; c < 4; c++)                                          \
                CPA16(db + ((c * 4) ^ swl) * 4, srcH + c * 4, sz);               \
        } } while (0)

    const int S = K1 / 32;  /* 36 */
    KAN_LOAD(0, 0); CPC();
#pragma unroll 1
    for (int s = 0; s < S; s++) {
        int buf = s & 1;
        if (s < S - 1) { KAN_LOAD(s + 1, buf ^ 1); CPC(); CPW1(); }
        else CPW0();
        __syncthreads();
        u32 Ab = smb + buf * 24576, Bb = Ab + 16384;
#pragma unroll
        for (int kk = 0; kk < 2; kk++) {
            u32 ah[2][4], al[2][4], bh[4][2];
#pragma unroll
            for (int mt = 0; mt < 2; mt++) {
                LDSM4(ah[mt], Ab + offAh[mt][kk]);
                LDSM4(al[mt], Ab + offAl[mt][kk]);
            }
#pragma unroll
            for (int p = 0; p < 2; p++) {
                u32 f[4];
                LDSM4(f, Bb + offBh[p][kk]);
                bh[2 * p][0] = f[0]; bh[2 * p][1] = f[1];
                bh[2 * p + 1][0] = f[2]; bh[2 * p + 1][1] = f[3];
            }
#pragma unroll
            for (int nt = 0; nt < 4; nt++)
#pragma unroll
                for (int mt = 0; mt < 2; mt++) {
                    MMA16816(acc[mt][nt], ah[mt], bh[nt][0], bh[nt][1]);
                    MMA16816(acc[mt][nt], al[mt], bh[nt][0], bh[nt][1]);
                }
        }
        __syncthreads();
    }
#undef KAN_LOAD

    /* fused kan2: hk through smem, out written directly */
    float* hk_s = (float*)sm;               /* [128][65] = 33.3 KB */
    float* s_w  = (float*)sm + 128 * 65;    /* [64][18]  = 4.6 KB  */
    for (int t = tid; t < 64 * 18; t += 256) {
        int i = t / 18, rem = t % 18, j = rem >> 1, o = rem & 1;
        s_w[t] = (j < 8) ? ks2[((size_t)o * 64 + i) * 8 + j] : kb2[o * 64 + i];
    }
    int grp = lane >> 2, tig = lane & 3;
#pragma unroll
    for (int mt = 0; mt < 2; mt++)
#pragma unroll
        for (int nt = 0; nt < 4; nt++) {
            int col = ncol0 + nt * 8 + 2 * tig;
            int rl0 = mrow0 + mt * 16 + grp;
            hk_s[rl0 * 65 + col]     = acc[mt][nt][0];
            hk_s[rl0 * 65 + col + 1] = acc[mt][nt][1];
            hk_s[(rl0 + 8) * 65 + col]     = acc[mt][nt][2];
            hk_s[(rl0 + 8) * 65 + col + 1] = acc[mt][nt][3];
        }
    __syncthreads();
    if (tid < 128) {
        int gn = m0 + tid;
        if (gn < N_NODES) {
            float o0 = 0.0f, o1 = 0.0f;
            for (int i = 0; i < 64; i++) {
                float xv = hk_s[tid * 65 + i];
                float b[8];
                bspline_basis(xv, b);
                float v8 = silu_f(xv);
                const float* w = &s_w[i * 18];
#pragma unroll
                for (int j = 0; j < 8; j++) {
                    o0 = fmaf(b[j], w[j * 2 + 0], o0);
                    o1 = fmaf(b[j], w[j * 2 + 1], o1);
                }
                o0 = fmaf(v8, w[16], o0);
                o1 = fmaf(v8, w[17], o1);
            }
            out[(size_t)gn * 2 + 0] = o0;
            out[(size_t)gn * 2 + 1] = o1;
        }
    }
}

/* ------------------------------------------------------------------ */
extern "C" void kernel_launch(void* const* d_in, const int* in_sizes, int n_in,
                              void* d_out, int out_size) {
    const float* x   = (const float*)d_in[0];
    const int*   e   = (const int*)d_in[1];
    const float* W1l = (const float*)d_in[2];
    const float* b1  = (const float*)d_in[3];
    const float* W1r = (const float*)d_in[4];
    const float* W2l = (const float*)d_in[5];
    const float* b2  = (const float*)d_in[6];
    const float* W2r = (const float*)d_in[7];
    const float* kb1 = (const float*)d_in[8];
    const float* ks1 = (const float*)d_in[9];
    const float* kb2 = (const float*)d_in[10];
    const float* ks2 = (const float*)d_in[11];
    float* out = (float*)d_out;

    (void)in_sizes; (void)n_in; (void)out_size;

    const int CONV_SMEM = 65536;
    const int KAN_SMEM  = 49152;
    cudaFuncSetAttribute(conv_mma2_kernel, cudaFuncAttributeMaxDynamicSharedMemorySize, CONV_SMEM);
    cudaFuncSetAttribute(kan1_mma2_kernel, cudaFuncAttributeMaxDynamicSharedMemorySize, KAN_SMEM);

    const int EB = (N_EDGES + 255) / 256;
    const int MT = (N_NODES + 127) / 128;   /* 391 */

    initA_kernel<<<(N_NODES * 64 + 255) / 256, 256>>>(e, x, W1l, W1r, W2l, W2r, kb1, ks1);
    convert_kernel<<<EB, 256>>>(e);          /* + histogram */
    scan1_kernel<<<NBLK, 256>>>();
    scan2_kernel<<<1, 256>>>();
    scan3_kernel<<<NBLK, 256>>>();
    scatter_kernel<<<EB, 256>>>();

    /* layer 1 */
    agg_kernel<<<(N_NODES + 7) / 8, 256>>>(x, 0);
    conv_mma2_kernel<<<MT, 256, CONV_SMEM>>>(b1, 0);
    /* layer 2 (+fused phi) */
    agg_kernel<<<(N_NODES + 7) / 8, 256>>>(x, 1);
    conv_mma2_kernel<<<MT, 256, CONV_SMEM>>>(b2, 1);
    /* KAN1 (+fused KAN2) */
    kan1_mma2_kernel<<<MT, 256, KAN_SMEM>>>(kb2, ks2, out);
}

// round 14
// speedup vs baseline: 1.2726x; 1.2726x over previous
#include <cuda_runtime.h>
#include <cuda_fp16.h>

#define N_NODES 50000
#define N_EDGES 625000
#define HID 128
#define KAN_HID 64
#define NB 9            /* 8 spline bases + silu as 9th */
#define K1 (HID*NB)     /* 1152 */
#define K1W (K1/2)      /* 576 packed words per phi row */
#define NBLK 196        /* ceil(N_NODES/256) */

typedef unsigned int u32;

/* ------------------------------------------------------------------ */
/* scratch (device globals; no allocations allowed)                    */
/* ------------------------------------------------------------------ */
__device__ int   g_is64_nz;           /* static zero-init; monotone 0->1 */
__device__ int   g_src[N_EDGES];
__device__ int   g_dst[N_EDGES];
__device__ int   g_ssrc[N_EDGES];
__device__ int   g_cnt[N_NODES];
__device__ int   g_off[N_NODES + 1];
__device__ int   g_cur[N_NODES];
__device__ int   g_bsum[256];
__device__ int   g_boff[256];
__device__ float g_h1[N_NODES * HID];
__device__ float g_h2[N_NODES * HID];
__device__ float g_hk[N_NODES * KAN_HID];
/* packed fp16 (2 per u32); A-side split hi/lo, B-side hi only         */
__device__ __align__(16) u32 g_aggh[N_NODES * 64], g_aggl[N_NODES * 64];
__device__ __align__(16) u32 g_xh[N_NODES * 64],   g_xl[N_NODES * 64];
__device__ __align__(16) u32 g_h1h[N_NODES * 64],  g_h1l[N_NODES * 64];
__device__ __align__(16) u32 g_phih[(size_t)N_NODES * K1W], g_phil[(size_t)N_NODES * K1W];
__device__ __align__(16) u32 g_w1h[HID * HID];   /* [c][128 words of k] */
__device__ __align__(16) u32 g_w2h[HID * HID];
__device__ __align__(16) u32 g_wch[KAN_HID * K1W];

/* grid value, matching jax: arange(-3, 9)*0.4 - 1 */
#define GRIDV(j) (0.4f * (float)((j) - 3) - 1.0f)

__device__ __forceinline__ void bspline_basis(float x, float* b /*[8]*/) {
    float t[11];
#pragma unroll
    for (int i = 0; i < 11; i++) {
        float g0 = GRIDV(i), g1 = GRIDV(i + 1);
        t[i] = (x >= g0 && x < g1) ? 1.0f : 0.0f;
    }
#pragma unroll
    for (int k = 1; k <= 3; k++) {
#pragma unroll
        for (int i = 0; i < 11; i++) {
            if (i < 11 - k) {
                float gi = GRIDV(i), gi1 = GRIDV(i + 1);
                float gik = GRIDV(i + k), gik1 = GRIDV(i + k + 1);
                t[i] = (x - gi) * (1.0f / (gik - gi)) * t[i]
                     + (gik1 - x) * (1.0f / (gik1 - gi1)) * t[i + 1];
            }
        }
    }
#pragma unroll
    for (int i = 0; i < 8; i++) b[i] = t[i];
}

__device__ __forceinline__ float silu_f(float x) {
    return x * (1.0f / (1.0f + __expf(-x)));
}

__device__ __forceinline__ u32 pack2h(float a, float b) {
    __half2 t = __floats2half2_rn(a, b);
    return *reinterpret_cast<u32*>(&t);
}
__device__ __forceinline__ void split2(float a, float b, u32& hi, u32& lo) {
    __half ah = __float2half_rn(a), bh = __float2half_rn(b);
    float ar = a - __half2float(ah);
    float br = b - __half2float(bh);
    __half2 h; h.x = ah; h.y = bh;
    hi = *reinterpret_cast<u32*>(&h);
    lo = pack2h(ar, br);
}

__device__ __forceinline__ u32 s2u(const void* p) {
    u32 a;
    asm("{ .reg .u64 t; cvta.to.shared.u64 t, %1; cvt.u32.u64 %0, t; }"
        : "=r"(a) : "l"(p));
    return a;
}

#define MMA16816(d, a, b0, b1)                                              \
    asm volatile("mma.sync.aligned.m16n8k16.row.col.f32.f16.f16.f32 "       \
                 "{%0,%1,%2,%3}, {%4,%5,%6,%7}, {%8,%9}, {%0,%1,%2,%3};\n"  \
                 : "+f"((d)[0]), "+f"((d)[1]), "+f"((d)[2]), "+f"((d)[3])   \
                 : "r"((a)[0]), "r"((a)[1]), "r"((a)[2]), "r"((a)[3]),      \
                   "r"(b0), "r"(b1))

#define LDSM4(f, addr)                                                      \
    asm volatile("ldmatrix.sync.aligned.m8n8.x4.shared.b16 {%0,%1,%2,%3}, [%4];" \
                 : "=r"((f)[0]), "=r"((f)[1]), "=r"((f)[2]), "=r"((f)[3])   \
                 : "r"(addr))

#define CPA16(dst, src, sz)                                                 \
    asm volatile("cp.async.cg.shared.global [%0], [%1], 16, %2;"            \
                 :: "r"(dst), "l"(src), "r"(sz) : "memory")
#define CPC()  asm volatile("cp.async.commit_group;" ::: "memory")
#define CPW1() asm volatile("cp.async.wait_group 1;" ::: "memory")
#define CPW0() asm volatile("cp.async.wait_group 0;" ::: "memory")

/* ------------------------------------------------------------------ */
/* fused: init counters + int64 detect + all weight/x fp16 conversion  */
/* ------------------------------------------------------------------ */
__global__ void initA_kernel(const int* __restrict__ e,
                             const float* __restrict__ x,
                             const float* __restrict__ W1l, const float* __restrict__ W1r,
                             const float* __restrict__ W2l, const float* __restrict__ W2r,
                             const float* __restrict__ kb1, const float* __restrict__ ks1) {
    int t = blockIdx.x * blockDim.x + threadIdx.x;
    if (t < N_NODES) g_cnt[t] = 0;
    if (t < 2048 && e[2 * t + 1] != 0) atomicOr(&g_is64_nz, 1);
    if (t < N_NODES * 64) {
        float2 v = ((const float2*)x)[t];
        split2(v.x, v.y, g_xh[t], g_xl[t]);
    }
    if (t < HID * HID) {
        int c = t >> 7, w = t & 127;
        int k0 = 2 * w, k1 = k0 + 1;
        float v0 = (k0 < 128) ? W1l[c * 128 + k0] : W1r[c * 128 + k0 - 128];
        float v1 = (k1 < 128) ? W1l[c * 128 + k1] : W1r[c * 128 + k1 - 128];
        g_w1h[t] = pack2h(v0, v1);
        v0 = (k0 < 128) ? W2l[c * 128 + k0] : W2r[c * 128 + k0 - 128];
        v1 = (k1 < 128) ? W2l[c * 128 + k1] : W2r[c * 128 + k1 - 128];
        g_w2h[t] = pack2h(v0, v1);
    }
    if (t < KAN_HID * K1W) {
        int o = t / K1W, w = t % K1W;
        int k0 = 2 * w, k1 = k0 + 1;
        int i0 = k0 / NB, j0 = k0 % NB;
        int i1 = k1 / NB, j1 = k1 % NB;
        float v0 = (j0 < 8) ? ks1[((size_t)o * 128 + i0) * 8 + j0] : kb1[o * 128 + i0];
        float v1 = (j1 < 8) ? ks1[((size_t)o * 128 + i1) * 8 + j1] : kb1[o * 128 + i1];
        g_wch[t] = pack2h(v0, v1);
    }
}

/* convert + histogram fused (reads g_is64_nz from previous kernel)    */
__global__ void convert_kernel(const int* __restrict__ e) {
    int i = blockIdx.x * blockDim.x + threadIdx.x;
    if (i >= N_EDGES) return;
    int s, d;
    if (g_is64_nz == 0) {
        s = e[2 * i];
        d = e[2 * N_EDGES + 2 * i];
    } else {
        s = e[i];
        d = e[N_EDGES + i];
    }
    g_src[i] = s;
    g_dst[i] = d;
    atomicAdd(&g_cnt[d], 1);
}

__device__ __forceinline__ int warp_incl_scan(int v) {
#pragma unroll
    for (int d = 1; d < 32; d <<= 1) {
        int t = __shfl_up_sync(0xffffffffu, v, d);
        if ((threadIdx.x & 31) >= d) v += t;
    }
    return v;
}

/* parallel 3-phase exclusive scan of g_cnt -> g_off / g_cur */
__global__ void scan1_kernel() {          /* grid NBLK x 256 */
    __shared__ int sh[8];
    int i = blockIdx.x * 256 + threadIdx.x;
    int v = (i < N_NODES) ? g_cnt[i] : 0;
    int lane = threadIdx.x & 31, w = threadIdx.x >> 5;
    int s = v;
#pragma unroll
    for (int d = 16; d > 0; d >>= 1) s += __shfl_down_sync(0xffffffffu, s, d);
    if (lane == 0) sh[w] = s;
    __syncthreads();
    if (threadIdx.x == 0) {
        int t = 0;
#pragma unroll
        for (int k = 0; k < 8; k++) t += sh[k];
        g_bsum[blockIdx.x] = t;
    }
}

__global__ void scan2_kernel() {          /* 1 block x 256 */
    __shared__ int sv[256];
    int i = threadIdx.x;
    int v = (i < NBLK) ? g_bsum[i] : 0;
    sv[i] = v;
    __syncthreads();
#pragma unroll
    for (int d = 1; d < 256; d <<= 1) {
        int t = (i >= d) ? sv[i - d] : 0;
        __syncthreads();
        sv[i] += t;
        __syncthreads();
    }
    if (i < NBLK) g_boff[i] = sv[i] - v;   /* exclusive */
    if (i == NBLK - 1) g_off[N_NODES] = sv[i];
}

__global__ void scan3_kernel() {          /* grid NBLK x 256 */
    __shared__ int wsums[8];
    int i = blockIdx.x * 256 + threadIdx.x;
    int v = (i < N_NODES) ? g_cnt[i] : 0;
    int lane = threadIdx.x & 31, w = threadIdx.x >> 5;
    int inc = warp_incl_scan(v);
    if (lane == 31) wsums[w] = inc;
    __syncthreads();
    int woff = 0;
    for (int k = 0; k < w; k++) woff += wsums[k];
    int excl = g_boff[blockIdx.x] + woff + inc - v;
    if (i < N_NODES) { g_off[i] = excl; g_cur[i] = excl; }
}

__global__ void scatter_kernel() {
    int i = blockIdx.x * blockDim.x + threadIdx.x;
    if (i >= N_EDGES) return;
    int d = g_dst[i];
    int p = atomicAdd(&g_cur[d], 1);
    g_ssrc[p] = g_src[i];
}

/* ------------------------------------------------------------------ */
/* mean aggregation: one warp per node, CSR, MLP=4; emits fp16 hi/lo   */
/* ------------------------------------------------------------------ */
__global__ void agg_kernel(const float* __restrict__ xext, int use_h1) {
    int gw = (blockIdx.x * blockDim.x + threadIdx.x) >> 5;
    if (gw >= N_NODES) return;
    const float* __restrict__ src = use_h1 ? g_h1 : xext;
    int lane = threadIdx.x & 31;
    int e0 = g_off[gw], e1 = g_off[gw + 1];
    float ax = 0.f, ay = 0.f, az = 0.f, aw = 0.f;
    int e = e0;
    int e4 = e0 + ((e1 - e0) & ~3);
    for (; e < e4; e += 4) {
        int s0 = g_ssrc[e], s1 = g_ssrc[e + 1], s2 = g_ssrc[e + 2], s3 = g_ssrc[e + 3];
        float4 v0 = __ldg((const float4*)(src + (size_t)s0 * HID) + lane);
        float4 v1 = __ldg((const float4*)(src + (size_t)s1 * HID) + lane);
        float4 v2 = __ldg((const float4*)(src + (size_t)s2 * HID) + lane);
        float4 v3 = __ldg((const float4*)(src + (size_t)s3 * HID) + lane);
        ax += v0.x + v1.x + v2.x + v3.x;
        ay += v0.y + v1.y + v2.y + v3.y;
        az += v0.z + v1.z + v2.z + v3.z;
        aw += v0.w + v1.w + v2.w + v3.w;
    }
    for (; e < e1; e++) {
        int s = g_ssrc[e];
        float4 v = __ldg((const float4*)(src + (size_t)s * HID) + lane);
        ax += v.x; ay += v.y; az += v.z; aw += v.w;
    }
    int c = e1 - e0;
    float inv = (c > 0) ? (1.0f / (float)c) : 0.0f;
    ax *= inv; ay *= inv; az *= inv; aw *= inv;
    u32 h0, l0, h1v, l1v;
    split2(ax, ay, h0, l0);
    split2(az, aw, h1v, l1v);
    size_t w0 = (size_t)gw * 64 + lane * 2;
    g_aggh[w0] = h0; g_aggh[w0 + 1] = h1v;
    g_aggl[w0] = l0; g_aggl[w0 + 1] = l1v;
}

/* ------------------------------------------------------------------ */
/* conv GEMM (mma.sync fp16 2-pass + cp.async + ldmatrix)              */
/* BM=128 BN=128 BK=32, 2-stage pipeline, 8 warps 4m x 2n              */
/* ------------------------------------------------------------------ */
__global__ __launch_bounds__(256, 1) void conv_mma2_kernel(const float* __restrict__ bias,
                                                           int layer) {
    extern __shared__ u32 sm[];
    const u32* __restrict__ Ah1 = g_aggh;
    const u32* __restrict__ Al1 = g_aggl;
    const u32* __restrict__ Ah2 = layer ? g_h1h : g_xh;
    const u32* __restrict__ Al2 = layer ? g_h1l : g_xl;
    const u32* __restrict__ Wh  = layer ? g_w2h : g_w1h;
    float* outp = layer ? g_h2 : g_h1;

    int tid = threadIdx.x, lane = tid & 31, wid = tid >> 5;
    int m0 = blockIdx.x * 128;
    u32 smb = s2u(sm);

    int lr = tid & 127;
    bool isA = tid < 128;
    int gmr = m0 + lr;
    int gmc = (gmr < N_NODES) ? gmr : 0;
    u32 sz = isA ? ((gmr < N_NODES) ? 16u : 0u) : 16u;
    u32 swl = (lr & 7) * 4;
    u32 dstb = smb + ((isA ? 0 : 4096) + lr * 32) * 4;

    int q = lane >> 3, rr = lane & 7;
    int mrow0 = (wid & 3) * 32, ncol0 = (wid >> 2) * 64;
    u32 offAh[2][2], offAl[2][2], offBh[4][2];
#pragma unroll
    for (int mt = 0; mt < 2; mt++)
#pragma unroll
        for (int kk = 0; kk < 2; kk++) {
            int row = mrow0 + mt * 16 + rr + (q & 1) * 8;
            u32 swz = (row & 7) * 4;
            offAh[mt][kk] = (row * 32 + ((kk * 8 + (q >> 1) * 4) ^ swz)) * 4;
            offAl[mt][kk] = (row * 32 + ((16 + kk * 8 + (q >> 1) * 4) ^ swz)) * 4;
        }
#pragma unroll
    for (int p = 0; p < 4; p++)
#pragma unroll
        for (int kk = 0; kk < 2; kk++) {
            int row = ncol0 + p * 16 + (q >> 1) * 8 + rr;
            u32 swz = (row & 7) * 4;
            offBh[p][kk] = (row * 32 + ((kk * 8 + (q & 1) * 4) ^ swz)) * 4;
        }

    float acc[2][8][4];
#pragma unroll
    for (int mt = 0; mt < 2; mt++)
#pragma unroll
        for (int nt = 0; nt < 8; nt++)
#pragma unroll
            for (int c = 0; c < 4; c++) acc[mt][nt][c] = 0.0f;

#define CONV_LOAD(s, buf) do {                                                   \
        u32 db = dstb + (buf) * 32768;                                           \
        if (isA) {                                                               \
            const u32 *srcH, *srcL;                                              \
            if ((s) < 4) { srcH = Ah1 + (size_t)gmc * 64 + (s) * 16;             \
                           srcL = Al1 + (size_t)gmc * 64 + (s) * 16; }           \
            else         { srcH = Ah2 + (size_t)gmc * 64 + ((s) - 4) * 16;       \
                           srcL = Al2 + (size_t)gmc * 64 + ((s) - 4) * 16; }     \
            _Pragma("unroll")                                                    \
            for (int c = 0; c < 4; c++) {                                        \
                CPA16(db + ((c * 4) ^ swl) * 4, srcH + c * 4, sz);               \
                CPA16(db + (((16 + c * 4)) ^ swl) * 4, srcL + c * 4, sz);        \
            }                                                                    \
        } else {                                                                 \
            const u32* srcH = Wh + (size_t)lr * 128 + (s) * 16;                  \
            _Pragma("unroll")                                                    \
            for (int c = 0; c < 4; c++)                                          \
                CPA16(db + ((c * 4) ^ swl) * 4, srcH + c * 4, sz);               \
        } } while (0)

    CONV_LOAD(0, 0); CPC();
#pragma unroll 1
    for (int s = 0; s < 8; s++) {
        int buf = s & 1;
        if (s < 7) { CONV_LOAD(s + 1, buf ^ 1); CPC(); CPW1(); }
        else CPW0();
        __syncthreads();
        u32 Ab = smb + buf * 32768, Bb = Ab + 16384;
#pragma unroll
        for (int kk = 0; kk < 2; kk++) {
            u32 ah[2][4], al[2][4], bh[8][2];
#pragma unroll
            for (int mt = 0; mt < 2; mt++) {
                LDSM4(ah[mt], Ab + offAh[mt][kk]);
                LDSM4(al[mt], Ab + offAl[mt][kk]);
            }
#pragma unroll
            for (int p = 0; p < 4; p++) {
                u32 f[4];
                LDSM4(f, Bb + offBh[p][kk]);
                bh[2 * p][0] = f[0]; bh[2 * p][1] = f[1];
                bh[2 * p + 1][0] = f[2]; bh[2 * p + 1][1] = f[3];
            }
#pragma unroll
            for (int nt = 0; nt < 8; nt++)
#pragma unroll
                for (int mt = 0; mt < 2; mt++) {
                    MMA16816(acc[mt][nt], ah[mt], bh[nt][0], bh[nt][1]);
                    MMA16816(acc[mt][nt], al[mt], bh[nt][0], bh[nt][1]);
                }
        }
        __syncthreads();
    }
#undef CONV_LOAD

    int grp = lane >> 2, tig = lane & 3;
#pragma unroll
    for (int mt = 0; mt < 2; mt++)
#pragma unroll
        for (int nt = 0; nt < 8; nt++) {
            int col = ncol0 + nt * 8 + 2 * tig;
            float bx = __ldg(bias + col), by = __ldg(bias + col + 1);
            int r0 = m0 + mrow0 + mt * 16 + grp;
            if (r0 < N_NODES) {
                float v0 = fmaxf(acc[mt][nt][0] + bx, 0.0f);
                float v1 = fmaxf(acc[mt][nt][1] + by, 0.0f);
                *(float2*)&outp[(size_t)r0 * 128 + col] = make_float2(v0, v1);
                if (layer == 0) {
                    u32 h, l; split2(v0, v1, h, l);
                    g_h1h[(size_t)r0 * 64 + (col >> 1)] = h;
                    g_h1l[(size_t)r0 * 64 + (col >> 1)] = l;
                }
            }
            int r1 = r0 + 8;
            if (r1 < N_NODES) {
                float v0 = fmaxf(acc[mt][nt][2] + bx, 0.0f);
                float v1 = fmaxf(acc[mt][nt][3] + by, 0.0f);
                *(float2*)&outp[(size_t)r1 * 128 + col] = make_float2(v0, v1);
                if (layer == 0) {
                    u32 h, l; split2(v0, v1, h, l);
                    g_h1h[(size_t)r1 * 64 + (col >> 1)] = h;
                    g_h1l[(size_t)r1 * 64 + (col >> 1)] = l;
                }
            }
        }
}

/* ------------------------------------------------------------------ */
/* Phi materialization in fp16 hi/lo                                   */
/* ------------------------------------------------------------------ */
__global__ void phi_kernel() {
    int t = blockIdx.x * blockDim.x + threadIdx.x;
    if (t >= N_NODES * 64) return;
    int n = t >> 6, ip = t & 63;
    float x0 = g_h2[(size_t)n * 128 + 2 * ip];
    float x1 = g_h2[(size_t)n * 128 + 2 * ip + 1];
    float v[18];
    bspline_basis(x0, v);      v[8]  = silu_f(x0);
    bspline_basis(x1, v + 9);  v[17] = silu_f(x1);
    u32* ph = g_phih + (size_t)n * K1W + ip * 9;
    u32* pl = g_phil + (size_t)n * K1W + ip * 9;
#pragma unroll
    for (int w = 0; w < 9; w++) {
        u32 h, l;
        split2(v[2 * w], v[2 * w + 1], h, l);
        ph[w] = h; pl[w] = l;
    }
}

/* ------------------------------------------------------------------ */
/* KAN1 GEMM (mma.sync fp16 2-pass + cp.async + ldmatrix)              */
/* BM=128 BN=64 BK=32, 36 stages, 8 warps 4m x 2n (warp 32x32)         */
/* ------------------------------------------------------------------ */
__global__ __launch_bounds__(256, 1) void kan1_mma2_kernel() {
    extern __shared__ u32 sm[];
    int tid = threadIdx.x, lane = tid & 31, wid = tid >> 5;
    int m0 = blockIdx.x * 128;
    u32 smb = s2u(sm);

    int lr = tid & 127;
    bool isA = tid < 128;
    bool isB = (tid >= 128) && (tid < 192);
    int gmr = m0 + lr;
    int gmc = (gmr < N_NODES) ? gmr : 0;
    u32 sz = isA ? ((gmr < N_NODES) ? 16u : 0u) : 16u;
    u32 swl = (lr & 7) * 4;
    u32 dstb = smb + ((isA ? 0 : 4096) + lr * 32) * 4;

    int q = lane >> 3, rr = lane & 7;
    int mrow0 = (wid & 3) * 32, ncol0 = (wid >> 2) * 32;
    u32 offAh[2][2], offAl[2][2], offBh[2][2];
#pragma unroll
    for (int mt = 0; mt < 2; mt++)
#pragma unroll
        for (int kk = 0; kk < 2; kk++) {
            int row = mrow0 + mt * 16 + rr + (q & 1) * 8;
            u32 swz = (row & 7) * 4;
            offAh[mt][kk] = (row * 32 + ((kk * 8 + (q >> 1) * 4) ^ swz)) * 4;
            offAl[mt][kk] = (row * 32 + ((16 + kk * 8 + (q >> 1) * 4) ^ swz)) * 4;
        }
#pragma unroll
    for (int p = 0; p < 2; p++)
#pragma unroll
        for (int kk = 0; kk < 2; kk++) {
            int row = ncol0 + p * 16 + (q >> 1) * 8 + rr;
            u32 swz = (row & 7) * 4;
            offBh[p][kk] = (row * 32 + ((kk * 8 + (q & 1) * 4) ^ swz)) * 4;
        }

    float acc[2][4][4];
#pragma unroll
    for (int mt = 0; mt < 2; mt++)
#pragma unroll
        for (int nt = 0; nt < 4; nt++)
#pragma unroll
            for (int c = 0; c < 4; c++) acc[mt][nt][c] = 0.0f;

#define KAN_LOAD(s, buf) do {                                                    \
        u32 db = dstb + (buf) * 24576;                                           \
        if (isA) {                                                               \
            const u32* srcH = g_phih + (size_t)gmc * K1W + (s) * 16;             \
            const u32* srcL = g_phil + (size_t)gmc * K1W + (s) * 16;             \
            _Pragma("unroll")                                                    \
            for (int c = 0; c < 4; c++) {                                        \
                CPA16(db + ((c * 4) ^ swl) * 4, srcH + c * 4, sz);               \
                CPA16(db + (((16 + c * 4)) ^ swl) * 4, srcL + c * 4, sz);        \
            }                                                                    \
        } else if (isB) {                                                        \
            const u32* srcH = g_wch + (size_t)lr * K1W + (s) * 16;               \
            _Pragma("unroll")                                                    \
            for (int c = 0; c < 4; c++)                                          \
                CPA16(db + ((c * 4) ^ swl) * 4, srcH + c * 4, sz);               \
        } } while (0)

    const int S = K1 / 32;  /* 36 */
    KAN_LOAD(0, 0); CPC();
#pragma unroll 1
    for (int s = 0; s < S; s++) {
        int buf = s & 1;
        if (s < S - 1) { KAN_LOAD(s + 1, buf ^ 1); CPC(); CPW1(); }
        else CPW0();
        __syncthreads();
        u32 Ab = smb + buf * 24576, Bb = Ab + 16384;
#pragma unroll
        for (int kk = 0; kk < 2; kk++) {
            u32 ah[2][4], al[2][4], bh[4][2];
#pragma unroll
            for (int mt = 0; mt < 2; mt++) {
                LDSM4(ah[mt], Ab + offAh[mt][kk]);
                LDSM4(al[mt], Ab + offAl[mt][kk]);
            }
#pragma unroll
            for (int p = 0; p < 2; p++) {
                u32 f[4];
                LDSM4(f, Bb + offBh[p][kk]);
                bh[2 * p][0] = f[0]; bh[2 * p][1] = f[1];
                bh[2 * p + 1][0] = f[2]; bh[2 * p + 1][1] = f[3];
            }
#pragma unroll
            for (int nt = 0; nt < 4; nt++)
#pragma unroll
                for (int mt = 0; mt < 2; mt++) {
                    MMA16816(acc[mt][nt], ah[mt], bh[nt][0], bh[nt][1]);
                    MMA16816(acc[mt][nt], al[mt], bh[nt][0], bh[nt][1]);
                }
        }
        __syncthreads();
    }
#undef KAN_LOAD

    int grp = lane >> 2, tig = lane & 3;
#pragma unroll
    for (int mt = 0; mt < 2; mt++)
#pragma unroll
        for (int nt = 0; nt < 4; nt++) {
            int col = ncol0 + nt * 8 + 2 * tig;
            int r0 = m0 + mrow0 + mt * 16 + grp;
            if (r0 < N_NODES)
                *(float2*)&g_hk[(size_t)r0 * 64 + col] =
                    make_float2(acc[mt][nt][0], acc[mt][nt][1]);
            int r1 = r0 + 8;
            if (r1 < N_NODES)
                *(float2*)&g_hk[(size_t)r1 * 64 + col] =
                    make_float2(acc[mt][nt][2], acc[mt][nt][3]);
        }
}

/* ------------------------------------------------------------------ */
/* KAN2: out[n][o] = sum_i basis(hk[n][i]) . w  (o = 0..1)             */
/* ------------------------------------------------------------------ */
__global__ __launch_bounds__(128) void kan2_kernel(const float* __restrict__ kb2,
                                                   const float* __restrict__ ks2,
                                                   float* __restrict__ out) {
    __shared__ float s_h[128 * 65];
    __shared__ float s_w[64 * 18];   /* [i][j(0..8)][o(0..1)] */
    int tid = threadIdx.x;
    for (int t = tid; t < 64 * 18; t += 128) {
        int i = t / 18, rem = t % 18, j = rem >> 1, o = rem & 1;
        s_w[t] = (j < 8) ? ks2[((size_t)o * 64 + i) * 8 + j] : kb2[o * 64 + i];
    }
    int n0 = blockIdx.x * 128;
    for (int t = tid; t < 128 * 64; t += 128) {
        int r = t >> 6, c = t & 63;
        int gn = n0 + r;
        s_h[r * 65 + c] = (gn < N_NODES) ? g_hk[(size_t)gn * 64 + c] : 0.0f;
    }
    __syncthreads();
    int gn = n0 + tid;
    if (gn >= N_NODES) return;
    float o0 = 0.0f, o1 = 0.0f;
    for (int i = 0; i < 64; i++) {
        float x = s_h[tid * 65 + i];
        float b[8];
        bspline_basis(x, b);
        float v8 = silu_f(x);
        const float* w = &s_w[i * 18];
#pragma unroll
        for (int j = 0; j < 8; j++) {
            o0 = fmaf(b[j], w[j * 2 + 0], o0);
            o1 = fmaf(b[j], w[j * 2 + 1], o1);
        }
        o0 = fmaf(v8, w[16], o0);
        o1 = fmaf(v8, w[17], o1);
    }
    out[(size_t)gn * 2 + 0] = o0;
    out[(size_t)gn * 2 + 1] = o1;
}

/* ------------------------------------------------------------------ */
extern "C" void kernel_launch(void* const* d_in, const int* in_sizes, int n_in,
                              void* d_out, int out_size) {
    const float* x   = (const float*)d_in[0];
    const int*   e   = (const int*)d_in[1];
    const float* W1l = (const float*)d_in[2];
    const float* b1  = (const float*)d_in[3];
    const float* W1r = (const float*)d_in[4];
    const float* W2l = (const float*)d_in[5];
    const float* b2  = (const float*)d_in[6];
    const float* W2r = (const float*)d_in[7];
    const float* kb1 = (const float*)d_in[8];
    const float* ks1 = (const float*)d_in[9];
    const float* kb2 = (const float*)d_in[10];
    const float* ks2 = (const float*)d_in[11];
    float* out = (float*)d_out;

    (void)in_sizes; (void)n_in; (void)out_size;

    const int CONV_SMEM = 65536;
    const int KAN_SMEM  = 49152;
    cudaFuncSetAttribute(conv_mma2_kernel, cudaFuncAttributeMaxDynamicSharedMemorySize, CONV_SMEM);
    cudaFuncSetAttribute(kan1_mma2_kernel, cudaFuncAttributeMaxDynamicSharedMemorySize, KAN_SMEM);

    const int EB = (N_EDGES + 255) / 256;
    const int MT = (N_NODES + 127) / 128;   /* 391 */

    initA_kernel<<<(N_NODES * 64 + 255) / 256, 256>>>(e, x, W1l, W1r, W2l, W2r, kb1, ks1);
    convert_kernel<<<EB, 256>>>(e);          /* + histogram */
    scan1_kernel<<<NBLK, 256>>>();
    scan2_kernel<<<1, 256>>>();
    scan3_kernel<<<NBLK, 256>>>();
    scatter_kernel<<<EB, 256>>>();

    /* layer 1 */
    agg_kernel<<<(N_NODES + 7) / 8, 256>>>(x, 0);
    conv_mma2_kernel<<<MT, 256, CONV_SMEM>>>(b1, 0);
    /* layer 2 */
    agg_kernel<<<(N_NODES + 7) / 8, 256>>>(x, 1);
    conv_mma2_kernel<<<MT, 256, CONV_SMEM>>>(b2, 1);
    /* KAN 1 */
    phi_kernel<<<(N_NODES * 64 + 255) / 256, 256>>>();
    kan1_mma2_kernel<<<MT, 256, KAN_SMEM>>>();
    /* KAN 2 */
    kan2_kernel<<<(N_NODES + 127) / 128, 128>>>(kb2, ks2, out);
}

// round 15
// speedup vs baseline: 1.9672x; 1.5458x over previous
#include <cuda_runtime.h>
#include <cuda_fp16.h>

#define N_NODES 50000
#define N_EDGES 625000
#define HID 128
#define KAN_HID 64
#define NB 9            /* 8 spline bases + silu as 9th */
#define K1 (HID*NB)     /* 1152 */
#define K1W (K1/2)      /* 576 packed words per phi row */
#define NBLK 196        /* ceil(N_NODES/256) */

typedef unsigned int u32;

/* ------------------------------------------------------------------ */
/* scratch (device globals; no allocations allowed)                    */
/* ------------------------------------------------------------------ */
__device__ int   g_is64_nz;           /* static zero-init; monotone 0->1 */
__device__ int   g_src[N_EDGES];
__device__ int   g_dst[N_EDGES];
__device__ int   g_ssrc[N_EDGES];
__device__ int   g_cnt[N_NODES];
__device__ int   g_off[N_NODES + 1];
__device__ int   g_cur[N_NODES];
__device__ int   g_bsum[256];
__device__ int   g_boff[256];
__device__ float g_h1[N_NODES * HID];
__device__ float g_h2[N_NODES * HID];
__device__ float g_hk[N_NODES * KAN_HID];
/* packed fp16 (2 per u32); conv A-side split hi/lo, B-side hi only    */
__device__ __align__(16) u32 g_aggh[N_NODES * 64], g_aggl[N_NODES * 64];
__device__ __align__(16) u32 g_xh[N_NODES * 64],   g_xl[N_NODES * 64];
__device__ __align__(16) u32 g_h1h[N_NODES * 64],  g_h1l[N_NODES * 64];
__device__ __align__(16) u32 g_phih[(size_t)N_NODES * K1W];   /* hi only */
__device__ __align__(16) u32 g_w1h[HID * HID];   /* [c][128 words of k] */
__device__ __align__(16) u32 g_w2h[HID * HID];
__device__ __align__(16) u32 g_wch[KAN_HID * K1W];

/* grid value, matching jax: arange(-3, 9)*0.4 - 1 */
#define GRIDV(j) (0.4f * (float)((j) - 3) - 1.0f)

__device__ __forceinline__ void bspline_basis(float x, float* b /*[8]*/) {
    float t[11];
#pragma unroll
    for (int i = 0; i < 11; i++) {
        float g0 = GRIDV(i), g1 = GRIDV(i + 1);
        t[i] = (x >= g0 && x < g1) ? 1.0f : 0.0f;
    }
#pragma unroll
    for (int k = 1; k <= 3; k++) {
#pragma unroll
        for (int i = 0; i < 11; i++) {
            if (i < 11 - k) {
                float gi = GRIDV(i), gi1 = GRIDV(i + 1);
                float gik = GRIDV(i + k), gik1 = GRIDV(i + k + 1);
                t[i] = (x - gi) * (1.0f / (gik - gi)) * t[i]
                     + (gik1 - x) * (1.0f / (gik1 - gi1)) * t[i + 1];
            }
        }
    }
#pragma unroll
    for (int i = 0; i < 8; i++) b[i] = t[i];
}

__device__ __forceinline__ float silu_f(float x) {
    return x * (1.0f / (1.0f + __expf(-x)));
}

__device__ __forceinline__ u32 pack2h(float a, float b) {
    __half2 t = __floats2half2_rn(a, b);
    return *reinterpret_cast<u32*>(&t);
}
__device__ __forceinline__ void split2(float a, float b, u32& hi, u32& lo) {
    __half ah = __float2half_rn(a), bh = __float2half_rn(b);
    float ar = a - __half2float(ah);
    float br = b - __half2float(bh);
    __half2 h; h.x = ah; h.y = bh;
    hi = *reinterpret_cast<u32*>(&h);
    lo = pack2h(ar, br);
}

__device__ __forceinline__ u32 s2u(const void* p) {
    u32 a;
    asm("{ .reg .u64 t; cvta.to.shared.u64 t, %1; cvt.u32.u64 %0, t; }"
        : "=r"(a) : "l"(p));
    return a;
}

#define MMA16816(d, a, b0, b1)                                              \
    asm volatile("mma.sync.aligned.m16n8k16.row.col.f32.f16.f16.f32 "       \
                 "{%0,%1,%2,%3}, {%4,%5,%6,%7}, {%8,%9}, {%0,%1,%2,%3};\n"  \
                 : "+f"((d)[0]), "+f"((d)[1]), "+f"((d)[2]), "+f"((d)[3])   \
                 : "r"((a)[0]), "r"((a)[1]), "r"((a)[2]), "r"((a)[3]),      \
                   "r"(b0), "r"(b1))

#define LDSM4(f, addr)                                                      \
    asm volatile("ldmatrix.sync.aligned.m8n8.x4.shared.b16 {%0,%1,%2,%3}, [%4];" \
                 : "=r"((f)[0]), "=r"((f)[1]), "=r"((f)[2]), "=r"((f)[3])   \
                 : "r"(addr))

#define CPA16(dst, src, sz)                                                 \
    asm volatile("cp.async.cg.shared.global [%0], [%1], 16, %2;"            \
                 :: "r"(dst), "l"(src), "r"(sz) : "memory")
#define CPC()  asm volatile("cp.async.commit_group;" ::: "memory")
#define CPW1() asm volatile("cp.async.wait_group 1;" ::: "memory")
#define CPW0() asm volatile("cp.async.wait_group 0;" ::: "memory")

/* ------------------------------------------------------------------ */
/* fused: init counters + int64 detect + all weight/x fp16 conversion  */
/* ------------------------------------------------------------------ */
__global__ void initA_kernel(const int* __restrict__ e,
                             const float* __restrict__ x,
                             const float* __restrict__ W1l, const float* __restrict__ W1r,
                             const float* __restrict__ W2l, const float* __restrict__ W2r,
                             const float* __restrict__ kb1, const float* __restrict__ ks1) {
    int t = blockIdx.x * blockDim.x + threadIdx.x;
    if (t < N_NODES) g_cnt[t] = 0;
    if (t < 2048 && e[2 * t + 1] != 0) atomicOr(&g_is64_nz, 1);
    if (t < N_NODES * 64) {
        float2 v = ((const float2*)x)[t];
        split2(v.x, v.y, g_xh[t], g_xl[t]);
    }
    if (t < HID * HID) {
        int c = t >> 7, w = t & 127;
        int k0 = 2 * w, k1 = k0 + 1;
        float v0 = (k0 < 128) ? W1l[c * 128 + k0] : W1r[c * 128 + k0 - 128];
        float v1 = (k1 < 128) ? W1l[c * 128 + k1] : W1r[c * 128 + k1 - 128];
        g_w1h[t] = pack2h(v0, v1);
        v0 = (k0 < 128) ? W2l[c * 128 + k0] : W2r[c * 128 + k0 - 128];
        v1 = (k1 < 128) ? W2l[c * 128 + k1] : W2r[c * 128 + k1 - 128];
        g_w2h[t] = pack2h(v0, v1);
    }
    if (t < KAN_HID * K1W) {
        int o = t / K1W, w = t % K1W;
        int k0 = 2 * w, k1 = k0 + 1;
        int i0 = k0 / NB, j0 = k0 % NB;
        int i1 = k1 / NB, j1 = k1 % NB;
        float v0 = (j0 < 8) ? ks1[((size_t)o * 128 + i0) * 8 + j0] : kb1[o * 128 + i0];
        float v1 = (j1 < 8) ? ks1[((size_t)o * 128 + i1) * 8 + j1] : kb1[o * 128 + i1];
        g_wch[t] = pack2h(v0, v1);
    }
}

/* convert + histogram fused (reads g_is64_nz from previous kernel)    */
__global__ void convert_kernel(const int* __restrict__ e) {
    int i = blockIdx.x * blockDim.x + threadIdx.x;
    if (i >= N_EDGES) return;
    int s, d;
    if (g_is64_nz == 0) {
        s = e[2 * i];
        d = e[2 * N_EDGES + 2 * i];
    } else {
        s = e[i];
        d = e[N_EDGES + i];
    }
    g_src[i] = s;
    g_dst[i] = d;
    atomicAdd(&g_cnt[d], 1);
}

__device__ __forceinline__ int warp_incl_scan(int v) {
#pragma unroll
    for (int d = 1; d < 32; d <<= 1) {
        int t = __shfl_up_sync(0xffffffffu, v, d);
        if ((threadIdx.x & 31) >= d) v += t;
    }
    return v;
}

/* parallel 3-phase exclusive scan of g_cnt -> g_off / g_cur */
__global__ void scan1_kernel() {          /* grid NBLK x 256 */
    __shared__ int sh[8];
    int i = blockIdx.x * 256 + threadIdx.x;
    int v = (i < N_NODES) ? g_cnt[i] : 0;
    int lane = threadIdx.x & 31, w = threadIdx.x >> 5;
    int s = v;
#pragma unroll
    for (int d = 16; d > 0; d >>= 1) s += __shfl_down_sync(0xffffffffu, s, d);
    if (lane == 0) sh[w] = s;
    __syncthreads();
    if (threadIdx.x == 0) {
        int t = 0;
#pragma unroll
        for (int k = 0; k < 8; k++) t += sh[k];
        g_bsum[blockIdx.x] = t;
    }
}

__global__ void scan2_kernel() {          /* 1 block x 256 */
    __shared__ int sv[256];
    int i = threadIdx.x;
    int v = (i < NBLK) ? g_bsum[i] : 0;
    sv[i] = v;
    __syncthreads();
#pragma unroll
    for (int d = 1; d < 256; d <<= 1) {
        int t = (i >= d) ? sv[i - d] : 0;
        __syncthreads();
        sv[i] += t;
        __syncthreads();
    }
    if (i < NBLK) g_boff[i] = sv[i] - v;   /* exclusive */
    if (i == NBLK - 1) g_off[N_NODES] = sv[i];
}

__global__ void scan3_kernel() {          /* grid NBLK x 256 */
    __shared__ int wsums[8];
    int i = blockIdx.x * 256 + threadIdx.x;
    int v = (i < N_NODES) ? g_cnt[i] : 0;
    int lane = threadIdx.x & 31, w = threadIdx.x >> 5;
    int inc = warp_incl_scan(v);
    if (lane == 31) wsums[w] = inc;
    __syncthreads();
    int woff = 0;
    for (int k = 0; k < w; k++) woff += wsums[k];
    int excl = g_boff[blockIdx.x] + woff + inc - v;
    if (i < N_NODES) { g_off[i] = excl; g_cur[i] = excl; }
}

__global__ void scatter_kernel() {
    int i = blockIdx.x * blockDim.x + threadIdx.x;
    if (i >= N_EDGES) return;
    int d = g_dst[i];
    int p = atomicAdd(&g_cur[d], 1);
    g_ssrc[p] = g_src[i];
}

/* ------------------------------------------------------------------ */
/* mean aggregation: one warp per node, CSR, MLP=4; emits fp16 hi/lo   */
/* ------------------------------------------------------------------ */
__global__ void agg_kernel(const float* __restrict__ xext, int use_h1) {
    int gw = (blockIdx.x * blockDim.x + threadIdx.x) >> 5;
    if (gw >= N_NODES) return;
    const float* __restrict__ src = use_h1 ? g_h1 : xext;
    int lane = threadIdx.x & 31;
    int e0 = g_off[gw], e1 = g_off[gw + 1];
    float ax = 0.f, ay = 0.f, az = 0.f, aw = 0.f;
    int e = e0;
    int e4 = e0 + ((e1 - e0) & ~3);
    for (; e < e4; e += 4) {
        int s0 = g_ssrc[e], s1 = g_ssrc[e + 1], s2 = g_ssrc[e + 2], s3 = g_ssrc[e + 3];
        float4 v0 = __ldg((const float4*)(src + (size_t)s0 * HID) + lane);
        float4 v1 = __ldg((const float4*)(src + (size_t)s1 * HID) + lane);
        float4 v2 = __ldg((const float4*)(src + (size_t)s2 * HID) + lane);
        float4 v3 = __ldg((const float4*)(src + (size_t)s3 * HID) + lane);
        ax += v0.x + v1.x + v2.x + v3.x;
        ay += v0.y + v1.y + v2.y + v3.y;
        az += v0.z + v1.z + v2.z + v3.z;
        aw += v0.w + v1.w + v2.w + v3.w;
    }
    for (; e < e1; e++) {
        int s = g_ssrc[e];
        float4 v = __ldg((const float4*)(src + (size_t)s * HID) + lane);
        ax += v.x; ay += v.y; az += v.z; aw += v.w;
    }
    int c = e1 - e0;
    float inv = (c > 0) ? (1.0f / (float)c) : 0.0f;
    ax *= inv; ay *= inv; az *= inv; aw *= inv;
    u32 h0, l0, h1v, l1v;
    split2(ax, ay, h0, l0);
    split2(az, aw, h1v, l1v);
    size_t w0 = (size_t)gw * 64 + lane * 2;
    g_aggh[w0] = h0; g_aggh[w0 + 1] = h1v;
    g_aggl[w0] = l0; g_aggl[w0 + 1] = l1v;
}

/* ------------------------------------------------------------------ */
/* conv GEMM (mma.sync fp16 2-pass + cp.async + ldmatrix)              */
/* BM=128 BN=128 BK=32, 2-stage pipeline, 8 warps 4m x 2n              */
/* ------------------------------------------------------------------ */
__global__ __launch_bounds__(256, 1) void conv_mma2_kernel(const float* __restrict__ bias,
                                                           int layer) {
    extern __shared__ u32 sm[];
    const u32* __restrict__ Ah1 = g_aggh;
    const u32* __restrict__ Al1 = g_aggl;
    const u32* __restrict__ Ah2 = layer ? g_h1h : g_xh;
    const u32* __restrict__ Al2 = layer ? g_h1l : g_xl;
    const u32* __restrict__ Wh  = layer ? g_w2h : g_w1h;
    float* outp = layer ? g_h2 : g_h1;

    int tid = threadIdx.x, lane = tid & 31, wid = tid >> 5;
    int m0 = blockIdx.x * 128;
    u32 smb = s2u(sm);

    int lr = tid & 127;
    bool isA = tid < 128;
    int gmr = m0 + lr;
    int gmc = (gmr < N_NODES) ? gmr : 0;
    u32 sz = isA ? ((gmr < N_NODES) ? 16u : 0u) : 16u;
    u32 swl = (lr & 7) * 4;
    u32 dstb = smb + ((isA ? 0 : 4096) + lr * 32) * 4;

    int q = lane >> 3, rr = lane & 7;
    int mrow0 = (wid & 3) * 32, ncol0 = (wid >> 2) * 64;
    u32 offAh[2][2], offAl[2][2], offBh[4][2];
#pragma unroll
    for (int mt = 0; mt < 2; mt++)
#pragma unroll
        for (int kk = 0; kk < 2; kk++) {
            int row = mrow0 + mt * 16 + rr + (q & 1) * 8;
            u32 swz = (row & 7) * 4;
            offAh[mt][kk] = (row * 32 + ((kk * 8 + (q >> 1) * 4) ^ swz)) * 4;
            offAl[mt][kk] = (row * 32 + ((16 + kk * 8 + (q >> 1) * 4) ^ swz)) * 4;
        }
#pragma unroll
    for (int p = 0; p < 4; p++)
#pragma unroll
        for (int kk = 0; kk < 2; kk++) {
            int row = ncol0 + p * 16 + (q >> 1) * 8 + rr;
            u32 swz = (row & 7) * 4;
            offBh[p][kk] = (row * 32 + ((kk * 8 + (q & 1) * 4) ^ swz)) * 4;
        }

    float acc[2][8][4];
#pragma unroll
    for (int mt = 0; mt < 2; mt++)
#pragma unroll
        for (int nt = 0; nt < 8; nt++)
#pragma unroll
            for (int c = 0; c < 4; c++) acc[mt][nt][c] = 0.0f;

#define CONV_LOAD(s, buf) do {                                                   \
        u32 db = dstb + (buf) * 32768;                                           \
        if (isA) {                                                               \
            const u32 *srcH, *srcL;                                              \
            if ((s) < 4) { srcH = Ah1 + (size_t)gmc * 64 + (s) * 16;             \
                           srcL = Al1 + (size_t)gmc * 64 + (s) * 16; }           \
            else         { srcH = Ah2 + (size_t)gmc * 64 + ((s) - 4) * 16;       \
                           srcL = Al2 + (size_t)gmc * 64 + ((s) - 4) * 16; }     \
            _Pragma("unroll")                                                    \
            for (int c = 0; c < 4; c++) {                                        \
                CPA16(db + ((c * 4) ^ swl) * 4, srcH + c * 4, sz);               \
                CPA16(db + (((16 + c * 4)) ^ swl) * 4, srcL + c * 4, sz);        \
            }                                                                    \
        } else {                                                                 \
            const u32* srcH = Wh + (size_t)lr * 128 + (s) * 16;                  \
            _Pragma("unroll")                                                    \
            for (int c = 0; c < 4; c++)                                          \
                CPA16(db + ((c * 4) ^ swl) * 4, srcH + c * 4, sz);               \
        } } while (0)

    CONV_LOAD(0, 0); CPC();
#pragma unroll 1
    for (int s = 0; s < 8; s++) {
        int buf = s & 1;
        if (s < 7) { CONV_LOAD(s + 1, buf ^ 1); CPC(); CPW1(); }
        else CPW0();
        __syncthreads();
        u32 Ab = smb + buf * 32768, Bb = Ab + 16384;
#pragma unroll
        for (int kk = 0; kk < 2; kk++) {
            u32 ah[2][4], al[2][4], bh[8][2];
#pragma unroll
            for (int mt = 0; mt < 2; mt++) {
                LDSM4(ah[mt], Ab + offAh[mt][kk]);
                LDSM4(al[mt], Ab + offAl[mt][kk]);
            }
#pragma unroll
            for (int p = 0; p < 4; p++) {
                u32 f[4];
                LDSM4(f, Bb + offBh[p][kk]);
                bh[2 * p][0] = f[0]; bh[2 * p][1] = f[1];
                bh[2 * p + 1][0] = f[2]; bh[2 * p + 1][1] = f[3];
            }
#pragma unroll
            for (int nt = 0; nt < 8; nt++)
#pragma unroll
                for (int mt = 0; mt < 2; mt++) {
                    MMA16816(acc[mt][nt], ah[mt], bh[nt][0], bh[nt][1]);
                    MMA16816(acc[mt][nt], al[mt], bh[nt][0], bh[nt][1]);
                }
        }
        __syncthreads();
    }
#undef CONV_LOAD

    int grp = lane >> 2, tig = lane & 3;
#pragma unroll
    for (int mt = 0; mt < 2; mt++)
#pragma unroll
        for (int nt = 0; nt < 8; nt++) {
            int col = ncol0 + nt * 8 + 2 * tig;
            float bx = __ldg(bias + col), by = __ldg(bias + col + 1);
            int r0 = m0 + mrow0 + mt * 16 + grp;
            if (r0 < N_NODES) {
                float v0 = fmaxf(acc[mt][nt][0] + bx, 0.0f);
                float v1 = fmaxf(acc[mt][nt][1] + by, 0.0f);
                *(float2*)&outp[(size_t)r0 * 128 + col] = make_float2(v0, v1);
                if (layer == 0) {
                    u32 h, l; split2(v0, v1, h, l);
                    g_h1h[(size_t)r0 * 64 + (col >> 1)] = h;
                    g_h1l[(size_t)r0 * 64 + (col >> 1)] = l;
                }
            }
            int r1 = r0 + 8;
            if (r1 < N_NODES) {
                float v0 = fmaxf(acc[mt][nt][2] + bx, 0.0f);
                float v1 = fmaxf(acc[mt][nt][3] + by, 0.0f);
                *(float2*)&outp[(size_t)r1 * 128 + col] = make_float2(v0, v1);
                if (layer == 0) {
                    u32 h, l; split2(v0, v1, h, l);
                    g_h1h[(size_t)r1 * 64 + (col >> 1)] = h;
                    g_h1l[(size_t)r1 * 64 + (col >> 1)] = l;
                }
            }
        }
}

/* ------------------------------------------------------------------ */
/* Phi materialization in fp16 (hi only — KAN1 is 1-pass now)          */
/* ------------------------------------------------------------------ */
__global__ void phi_kernel() {
    int t = blockIdx.x * blockDim.x + threadIdx.x;
    if (t >= N_NODES * 64) return;
    int n = t >> 6, ip = t & 63;
    float x0 = g_h2[(size_t)n * 128 + 2 * ip];
    float x1 = g_h2[(size_t)n * 128 + 2 * ip + 1];
    float v[18];
    bspline_basis(x0, v);      v[8]  = silu_f(x0);
    bspline_basis(x1, v + 9);  v[17] = silu_f(x1);
    u32* ph = g_phih + (size_t)n * K1W + ip * 9;
#pragma unroll
    for (int w = 0; w < 9; w++)
        ph[w] = pack2h(v[2 * w], v[2 * w + 1]);
}

/* ------------------------------------------------------------------ */
/* KAN1 GEMM (mma.sync fp16 1-PASS + cp.async + ldmatrix)              */
/* BM=128 BN=64 BK=32, 36 stages, 8 warps 4m x 2n (warp 32x32)         */
/* smem layout unchanged (lo half of A rows dead)                      */
/* ------------------------------------------------------------------ */
__global__ __launch_bounds__(256, 1) void kan1_mma2_kernel() {
    extern __shared__ u32 sm[];
    int tid = threadIdx.x, lane = tid & 31, wid = tid >> 5;
    int m0 = blockIdx.x * 128;
    u32 smb = s2u(sm);

    int lr = tid & 127;
    bool isA = tid < 128;
    bool isB = (tid >= 128) && (tid < 192);
    int gmr = m0 + lr;
    int gmc = (gmr < N_NODES) ? gmr : 0;
    u32 sz = isA ? ((gmr < N_NODES) ? 16u : 0u) : 16u;
    u32 swl = (lr & 7) * 4;
    u32 dstb = smb + ((isA ? 0 : 4096) + lr * 32) * 4;

    int q = lane >> 3, rr = lane & 7;
    int mrow0 = (wid & 3) * 32, ncol0 = (wid >> 2) * 32;
    u32 offAh[2][2], offBh[2][2];
#pragma unroll
    for (int mt = 0; mt < 2; mt++)
#pragma unroll
        for (int kk = 0; kk < 2; kk++) {
            int row = mrow0 + mt * 16 + rr + (q & 1) * 8;
            u32 swz = (row & 7) * 4;
            offAh[mt][kk] = (row * 32 + ((kk * 8 + (q >> 1) * 4) ^ swz)) * 4;
        }
#pragma unroll
    for (int p = 0; p < 2; p++)
#pragma unroll
        for (int kk = 0; kk < 2; kk++) {
            int row = ncol0 + p * 16 + (q >> 1) * 8 + rr;
            u32 swz = (row & 7) * 4;
            offBh[p][kk] = (row * 32 + ((kk * 8 + (q & 1) * 4) ^ swz)) * 4;
        }

    float acc[2][4][4];
#pragma unroll
    for (int mt = 0; mt < 2; mt++)
#pragma unroll
        for (int nt = 0; nt < 4; nt++)
#pragma unroll
            for (int c = 0; c < 4; c++) acc[mt][nt][c] = 0.0f;

#define KAN_LOAD(s, buf) do {                                                    \
        u32 db = dstb + (buf) * 24576;                                           \
        if (isA) {                                                               \
            const u32* srcH = g_phih + (size_t)gmc * K1W + (s) * 16;             \
            _Pragma("unroll")                                                    \
            for (int c = 0; c < 4; c++)                                          \
                CPA16(db + ((c * 4) ^ swl) * 4, srcH + c * 4, sz);               \
        } else if (isB) {                                                        \
            const u32* srcH = g_wch + (size_t)lr * K1W + (s) * 16;               \
            _Pragma("unroll")                                                    \
            for (int c = 0; c < 4; c++)                                          \
                CPA16(db + ((c * 4) ^ swl) * 4, srcH + c * 4, sz);               \
        } } while (0)

    const int S = K1 / 32;  /* 36 */
    KAN_LOAD(0, 0); CPC();
#pragma unroll 1
    for (int s = 0; s < S; s++) {
        int buf = s & 1;
        if (s < S - 1) { KAN_LOAD(s + 1, buf ^ 1); CPC(); CPW1(); }
        else CPW0();
        __syncthreads();
        u32 Ab = smb + buf * 24576, Bb = Ab + 16384;
#pragma unroll
        for (int kk = 0; kk < 2; kk++) {
            u32 ah[2][4], bh[4][2];
#pragma unroll
            for (int mt = 0; mt < 2; mt++)
                LDSM4(ah[mt], Ab + offAh[mt][kk]);
#pragma unroll
            for (int p = 0; p < 2; p++) {
                u32 f[4];
                LDSM4(f, Bb + offBh[p][kk]);
                bh[2 * p][0] = f[0]; bh[2 * p][1] = f[1];
                bh[2 * p + 1][0] = f[2]; bh[2 * p + 1][1] = f[3];
            }
#pragma unroll
            for (int nt = 0; nt < 4; nt++)
#pragma unroll
                for (int mt = 0; mt < 2; mt++)
                    MMA16816(acc[mt][nt], ah[mt], bh[nt][0], bh[nt][1]);
        }
        __syncthreads();
    }
#undef KAN_LOAD

    int grp = lane >> 2, tig = lane & 3;
#pragma unroll
    for (int mt = 0; mt < 2; mt++)
#pragma unroll
        for (int nt = 0; nt < 4; nt++) {
            int col = ncol0 + nt * 8 + 2 * tig;
            int r0 = m0 + mrow0 + mt * 16 + grp;
            if (r0 < N_NODES)
                *(float2*)&g_hk[(size_t)r0 * 64 + col] =
                    make_float2(acc[mt][nt][0], acc[mt][nt][1]);
            int r1 = r0 + 8;
            if (r1 < N_NODES)
                *(float2*)&g_hk[(size_t)r1 * 64 + col] =
                    make_float2(acc[mt][nt][2], acc[mt][nt][3]);
        }
}

/* ------------------------------------------------------------------ */
/* KAN2: out[n][o] = sum_i basis(hk[n][i]) . w  (o = 0..1)             */
/* ------------------------------------------------------------------ */
__global__ __launch_bounds__(128) void kan2_kernel(const float* __restrict__ kb2,
                                                   const float* __restrict__ ks2,
                                                   float* __restrict__ out) {
    __shared__ float s_h[128 * 65];
    __shared__ float s_w[64 * 18];   /* [i][j(0..8)][o(0..1)] */
    int tid = threadIdx.x;
    for (int t = tid; t < 64 * 18; t += 128) {
        int i = t / 18, rem = t % 18, j = rem >> 1, o = rem & 1;
        s_w[t] = (j < 8) ? ks2[((size_t)o * 64 + i) * 8 + j] : kb2[o * 64 + i];
    }
    int n0 = blockIdx.x * 128;
    for (int t = tid; t < 128 * 64; t += 128) {
        int r = t >> 6, c = t & 63;
        int gn = n0 + r;
        s_h[r * 65 + c] = (gn < N_NODES) ? g_hk[(size_t)gn * 64 + c] : 0.0f;
    }
    __syncthreads();
    int gn = n0 + tid;
    if (gn >= N_NODES) return;
    float o0 = 0.0f, o1 = 0.0f;
    for (int i = 0; i < 64; i++) {
        float x = s_h[tid * 65 + i];
        float b[8];
        bspline_basis(x, b);
        float v8 = silu_f(x);
        const float* w = &s_w[i * 18];
#pragma unroll
        for (int j = 0; j < 8; j++) {
            o0 = fmaf(b[j], w[j * 2 + 0], o0);
            o1 = fmaf(b[j], w[j * 2 + 1], o1);
        }
        o0 = fmaf(v8, w[16], o0);
        o1 = fmaf(v8, w[17], o1);
    }
    out[(size_t)gn * 2 + 0] = o0;
    out[(size_t)gn * 2 + 1] = o1;
}

/* ------------------------------------------------------------------ */
extern "C" void kernel_launch(void* const* d_in, const int* in_sizes, int n_in,
                              void* d_out, int out_size) {
    const float* x   = (const float*)d_in[0];
    const int*   e   = (const int*)d_in[1];
    const float* W1l = (const float*)d_in[2];
    const float* b1  = (const float*)d_in[3];
    const float* W1r = (const float*)d_in[4];
    const float* W2l = (const float*)d_in[5];
    const float* b2  = (const float*)d_in[6];
    const float* W2r = (const float*)d_in[7];
    const float* kb1 = (const float*)d_in[8];
    const float* ks1 = (const float*)d_in[9];
    const float* kb2 = (const float*)d_in[10];
    const float* ks2 = (const float*)d_in[11];
    float* out = (float*)d_out;

    (void)in_sizes; (void)n_in; (void)out_size;

    const int CONV_SMEM = 65536;
    const int KAN_SMEM  = 49152;
    cudaFuncSetAttribute(conv_mma2_kernel, cudaFuncAttributeMaxDynamicSharedMemorySize, CONV_SMEM);
    cudaFuncSetAttribute(kan1_mma2_kernel, cudaFuncAttributeMaxDynamicSharedMemorySize, KAN_SMEM);

    const int EB = (N_EDGES + 255) / 256;
    const int MT = (N_NODES + 127) / 128;   /* 391 */

    initA_kernel<<<(N_NODES * 64 + 255) / 256, 256>>>(e, x, W1l, W1r, W2l, W2r, kb1, ks1);
    convert_kernel<<<EB, 256>>>(e);          /* + histogram */
    scan1_kernel<<<NBLK, 256>>>();
    scan2_kernel<<<1, 256>>>();
    scan3_kernel<<<NBLK, 256>>>();
    scatter_kernel<<<EB, 256>>>();

    /* layer 1 */
    agg_kernel<<<(N_NODES + 7) / 8, 256>>>(x, 0);
    conv_mma2_kernel<<<MT, 256, CONV_SMEM>>>(b1, 0);
    /* layer 2 */
    agg_kernel<<<(N_NODES + 7) / 8, 256>>>(x, 1);
    conv_mma2_kernel<<<MT, 256, CONV_SMEM>>>(b2, 1);
    /* KAN 1 */
    phi_kernel<<<(N_NODES * 64 + 255) / 256, 256>>>();
    kan1_mma2_kernel<<<MT, 256, KAN_SMEM>>>();
    /* KAN 2 */
    kan2_kernel<<<(N_NODES + 127) / 128, 128>>>(kb2, ks2, out);
}

// round 17
// speedup vs baseline: 2.1502x; 1.0930x over previous
#include <cuda_runtime.h>
#include <cuda_fp16.h>

#define N_NODES 50000
#define N_EDGES 625000
#define HID 128
#define KAN_HID 64
#define NB 9            /* 8 spline bases + silu as 9th */
#define K1 (HID*NB)     /* 1152 */
#define K1W (K1/2)      /* 576 packed words per phi row */
#define NBLK 196        /* ceil(N_NODES/256) */

typedef unsigned int u32;

/* ------------------------------------------------------------------ */
/* scratch (device globals; no allocations allowed)                    */
/* ------------------------------------------------------------------ */
__device__ int   g_is64_nz;           /* static zero-init; monotone 0->1 */
__device__ int   g_src[N_EDGES];
__device__ int   g_dst[N_EDGES];
__device__ int   g_ssrc[N_EDGES];
__device__ int   g_cnt[N_NODES];
__device__ int   g_off[N_NODES + 1];
__device__ int   g_cur[N_NODES];
__device__ int   g_bsum[256];
__device__ int   g_boff[256];
__device__ float g_h1[N_NODES * HID];
__device__ float g_h2[N_NODES * HID];
__device__ float g_hk[N_NODES * KAN_HID];
/* packed fp16 (2 per u32); all GEMMs 1-pass (hi only)                 */
__device__ __align__(16) u32 g_aggh[N_NODES * 64];
__device__ __align__(16) u32 g_xh[N_NODES * 64];
__device__ __align__(16) u32 g_h1h[N_NODES * 64];
__device__ __align__(16) u32 g_phih[(size_t)N_NODES * K1W];
__device__ __align__(16) u32 g_w1h[HID * HID];   /* [c][128 words of k] */
__device__ __align__(16) u32 g_w2h[HID * HID];
__device__ __align__(16) u32 g_wch[KAN_HID * K1W];

/* grid value, matching jax: arange(-3, 9)*0.4 - 1 */
#define GRIDV(j) (0.4f * (float)((j) - 3) - 1.0f)

__device__ __forceinline__ void bspline_basis(float x, float* b /*[8]*/) {
    float t[11];
#pragma unroll
    for (int i = 0; i < 11; i++) {
        float g0 = GRIDV(i), g1 = GRIDV(i + 1);
        t[i] = (x >= g0 && x < g1) ? 1.0f : 0.0f;
    }
#pragma unroll
    for (int k = 1; k <= 3; k++) {
#pragma unroll
        for (int i = 0; i < 11; i++) {
            if (i < 11 - k) {
                float gi = GRIDV(i), gi1 = GRIDV(i + 1);
                float gik = GRIDV(i + k), gik1 = GRIDV(i + k + 1);
                t[i] = (x - gi) * (1.0f / (gik - gi)) * t[i]
                     + (gik1 - x) * (1.0f / (gik1 - gi1)) * t[i + 1];
            }
        }
    }
#pragma unroll
    for (int i = 0; i < 8; i++) b[i] = t[i];
}

__device__ __forceinline__ float silu_f(float x) {
    return x * (1.0f / (1.0f + __expf(-x)));
}

__device__ __forceinline__ u32 pack2h(float a, float b) {
    __half2 t = __floats2half2_rn(a, b);
    return *reinterpret_cast<u32*>(&t);
}

__device__ __forceinline__ u32 s2u(const void* p) {
    u32 a;
    asm("{ .reg .u64 t; cvta.to.shared.u64 t, %1; cvt.u32.u64 %0, t; }"
        : "=r"(a) : "l"(p));
    return a;
}

#define MMA16816(d, a, b0, b1)                                              \
    asm volatile("mma.sync.aligned.m16n8k16.row.col.f32.f16.f16.f32 "       \
                 "{%0,%1,%2,%3}, {%4,%5,%6,%7}, {%8,%9}, {%0,%1,%2,%3};\n"  \
                 : "+f"((d)[0]), "+f"((d)[1]), "+f"((d)[2]), "+f"((d)[3])   \
                 : "r"((a)[0]), "r"((a)[1]), "r"((a)[2]), "r"((a)[3]),      \
                   "r"(b0), "r"(b1))

#define LDSM4(f, addr)                                                      \
    asm volatile("ldmatrix.sync.aligned.m8n8.x4.shared.b16 {%0,%1,%2,%3}, [%4];" \
                 : "=r"((f)[0]), "=r"((f)[1]), "=r"((f)[2]), "=r"((f)[3])   \
                 : "r"(addr))

#define CPA16(dst, src, sz)                                                 \
    asm volatile("cp.async.cg.shared.global [%0], [%1], 16, %2;"            \
                 :: "r"(dst), "l"(src), "r"(sz) : "memory")
#define CPC()  asm volatile("cp.async.commit_group;" ::: "memory")
#define CPW1() asm volatile("cp.async.wait_group 1;" ::: "memory")
#define CPW0() asm volatile("cp.async.wait_group 0;" ::: "memory")

/* ------------------------------------------------------------------ */
/* fused: init counters + int64 detect + all weight/x fp16 conversion  */
/* ------------------------------------------------------------------ */
__global__ void initA_kernel(const int* __restrict__ e,
                             const float* __restrict__ x,
                             const float* __restrict__ W1l, const float* __restrict__ W1r,
                             const float* __restrict__ W2l, const float* __restrict__ W2r,
                             const float* __restrict__ kb1, const float* __restrict__ ks1) {
    int t = blockIdx.x * blockDim.x + threadIdx.x;
    if (t < N_NODES) g_cnt[t] = 0;
    if (t < 2048 && e[2 * t + 1] != 0) atomicOr(&g_is64_nz, 1);
    if (t < N_NODES * 64) {
        float2 v = ((const float2*)x)[t];
        g_xh[t] = pack2h(v.x, v.y);
    }
    if (t < HID * HID) {
        int c = t >> 7, w = t & 127;
        int k0 = 2 * w, k1 = k0 + 1;
        float v0 = (k0 < 128) ? W1l[c * 128 + k0] : W1r[c * 128 + k0 - 128];
        float v1 = (k1 < 128) ? W1l[c * 128 + k1] : W1r[c * 128 + k1 - 128];
        g_w1h[t] = pack2h(v0, v1);
        v0 = (k0 < 128) ? W2l[c * 128 + k0] : W2r[c * 128 + k0 - 128];
        v1 = (k1 < 128) ? W2l[c * 128 + k1] : W2r[c * 128 + k1 - 128];
        g_w2h[t] = pack2h(v0, v1);
    }
    if (t < KAN_HID * K1W) {
        int o = t / K1W, w = t % K1W;
        int k0 = 2 * w, k1 = k0 + 1;
        int i0 = k0 / NB, j0 = k0 % NB;
        int i1 = k1 / NB, j1 = k1 % NB;
        float v0 = (j0 < 8) ? ks1[((size_t)o * 128 + i0) * 8 + j0] : kb1[o * 128 + i0];
        float v1 = (j1 < 8) ? ks1[((size_t)o * 128 + i1) * 8 + j1] : kb1[o * 128 + i1];
        g_wch[t] = pack2h(v0, v1);
    }
}

/* convert + histogram fused (reads g_is64_nz from previous kernel)    */
__global__ void convert_kernel(const int* __restrict__ e) {
    int i = blockIdx.x * blockDim.x + threadIdx.x;
    if (i >= N_EDGES) return;
    int s, d;
    if (g_is64_nz == 0) {
        s = e[2 * i];
        d = e[2 * N_EDGES + 2 * i];
    } else {
        s = e[i];
        d = e[N_EDGES + i];
    }
    g_src[i] = s;
    g_dst[i] = d;
    atomicAdd(&g_cnt[d], 1);
}

__device__ __forceinline__ int warp_incl_scan(int v) {
#pragma unroll
    for (int d = 1; d < 32; d <<= 1) {
        int t = __shfl_up_sync(0xffffffffu, v, d);
        if ((threadIdx.x & 31) >= d) v += t;
    }
    return v;
}

/* parallel 3-phase exclusive scan of g_cnt -> g_off / g_cur */
__global__ void scan1_kernel() {          /* grid NBLK x 256 */
    __shared__ int sh[8];
    int i = blockIdx.x * 256 + threadIdx.x;
    int v = (i < N_NODES) ? g_cnt[i] : 0;
    int lane = threadIdx.x & 31, w = threadIdx.x >> 5;
    int s = v;
#pragma unroll
    for (int d = 16; d > 0; d >>= 1) s += __shfl_down_sync(0xffffffffu, s, d);
    if (lane == 0) sh[w] = s;
    __syncthreads();
    if (threadIdx.x == 0) {
        int t = 0;
#pragma unroll
        for (int k = 0; k < 8; k++) t += sh[k];
        g_bsum[blockIdx.x] = t;
    }
}

__global__ void scan2_kernel() {          /* 1 block x 256 */
    __shared__ int sv[256];
    int i = threadIdx.x;
    int v = (i < NBLK) ? g_bsum[i] : 0;
    sv[i] = v;
    __syncthreads();
#pragma unroll
    for (int d = 1; d < 256; d <<= 1) {
        int t = (i >= d) ? sv[i - d] : 0;
        __syncthreads();
        sv[i] += t;
        __syncthreads();
    }
    if (i < NBLK) g_boff[i] = sv[i] - v;   /* exclusive */
    if (i == NBLK - 1) g_off[N_NODES] = sv[i];
}

__global__ void scan3_kernel() {          /* grid NBLK x 256 */
    __shared__ int wsums[8];
    int i = blockIdx.x * 256 + threadIdx.x;
    int v = (i < N_NODES) ? g_cnt[i] : 0;
    int lane = threadIdx.x & 31, w = threadIdx.x >> 5;
    int inc = warp_incl_scan(v);
    if (lane == 31) wsums[w] = inc;
    __syncthreads();
    int woff = 0;
    for (int k = 0; k < w; k++) woff += wsums[k];
    int excl = g_boff[blockIdx.x] + woff + inc - v;
    if (i < N_NODES) { g_off[i] = excl; g_cur[i] = excl; }
}

__global__ void scatter_kernel() {
    int i = blockIdx.x * blockDim.x + threadIdx.x;
    if (i >= N_EDGES) return;
    int d = g_dst[i];
    int p = atomicAdd(&g_cur[d], 1);
    g_ssrc[p] = g_src[i];
}

/* ------------------------------------------------------------------ */
/* mean aggregation: one warp per node, CSR, MLP=4; emits fp16 hi      */
/* ------------------------------------------------------------------ */
__global__ void agg_kernel(const float* __restrict__ xext, int use_h1) {
    int gw = (blockIdx.x * blockDim.x + threadIdx.x) >> 5;
    if (gw >= N_NODES) return;
    const float* __restrict__ src = use_h1 ? g_h1 : xext;
    int lane = threadIdx.x & 31;
    int e0 = g_off[gw], e1 = g_off[gw + 1];
    float ax = 0.f, ay = 0.f, az = 0.f, aw = 0.f;
    int e = e0;
    int e4 = e0 + ((e1 - e0) & ~3);
    for (; e < e4; e += 4) {
        int s0 = g_ssrc[e], s1 = g_ssrc[e + 1], s2 = g_ssrc[e + 2], s3 = g_ssrc[e + 3];
        float4 v0 = __ldg((const float4*)(src + (size_t)s0 * HID) + lane);
        float4 v1 = __ldg((const float4*)(src + (size_t)s1 * HID) + lane);
        float4 v2 = __ldg((const float4*)(src + (size_t)s2 * HID) + lane);
        float4 v3 = __ldg((const float4*)(src + (size_t)s3 * HID) + lane);
        ax += v0.x + v1.x + v2.x + v3.x;
        ay += v0.y + v1.y + v2.y + v3.y;
        az += v0.z + v1.z + v2.z + v3.z;
        aw += v0.w + v1.w + v2.w + v3.w;
    }
    for (; e < e1; e++) {
        int s = g_ssrc[e];
        float4 v = __ldg((const float4*)(src + (size_t)s * HID) + lane);
        ax += v.x; ay += v.y; az += v.z; aw += v.w;
    }
    int c = e1 - e0;
    float inv = (c > 0) ? (1.0f / (float)c) : 0.0f;
    ax *= inv; ay *= inv; az *= inv; aw *= inv;
    size_t w0 = (size_t)gw * 64 + lane * 2;
    g_aggh[w0]     = pack2h(ax, ay);
    g_aggh[w0 + 1] = pack2h(az, aw);
}

/* ------------------------------------------------------------------ */
/* conv GEMM (mma.sync fp16 1-PASS + cp.async + ldmatrix)              */
/* BM=128 BN=128 BK=32, 2-stage pipeline, 8 warps 4m x 2n              */
/* smem layout unchanged (lo half of rows dead)                        */
/* ------------------------------------------------------------------ */
__global__ __launch_bounds__(256, 1) void conv_mma2_kernel(const float* __restrict__ bias,
                                                           int layer) {
    extern __shared__ u32 sm[];
    const u32* __restrict__ Ah1 = g_aggh;
    const u32* __restrict__ Ah2 = layer ? g_h1h : g_xh;
    const u32* __restrict__ Wh  = layer ? g_w2h : g_w1h;
    float* outp = layer ? g_h2 : g_h1;

    int tid = threadIdx.x, lane = tid & 31, wid = tid >> 5;
    int m0 = blockIdx.x * 128;
    u32 smb = s2u(sm);

    int lr = tid & 127;
    bool isA = tid < 128;
    int gmr = m0 + lr;
    int gmc = (gmr < N_NODES) ? gmr : 0;
    u32 sz = isA ? ((gmr < N_NODES) ? 16u : 0u) : 16u;
    u32 swl = (lr & 7) * 4;
    u32 dstb = smb + ((isA ? 0 : 4096) + lr * 32) * 4;

    int q = lane >> 3, rr = lane & 7;
    int mrow0 = (wid & 3) * 32, ncol0 = (wid >> 2) * 64;
    u32 offAh[2][2], offBh[4][2];
#pragma unroll
    for (int mt = 0; mt < 2; mt++)
#pragma unroll
        for (int kk = 0; kk < 2; kk++) {
            int row = mrow0 + mt * 16 + rr + (q & 1) * 8;
            u32 swz = (row & 7) * 4;
            offAh[mt][kk] = (row * 32 + ((kk * 8 + (q >> 1) * 4) ^ swz)) * 4;
        }
#pragma unroll
    for (int p = 0; p < 4; p++)
#pragma unroll
        for (int kk = 0; kk < 2; kk++) {
            int row = ncol0 + p * 16 + (q >> 1) * 8 + rr;
            u32 swz = (row & 7) * 4;
            offBh[p][kk] = (row * 32 + ((kk * 8 + (q & 1) * 4) ^ swz)) * 4;
        }

    float acc[2][8][4];
#pragma unroll
    for (int mt = 0; mt < 2; mt++)
#pragma unroll
        for (int nt = 0; nt < 8; nt++)
#pragma unroll
            for (int c = 0; c < 4; c++) acc[mt][nt][c] = 0.0f;

#define CONV_LOAD(s, buf) do {                                                   \
        u32 db = dstb + (buf) * 32768;                                           \
        const u32* srcH;                                                         \
        if (isA) {                                                               \
            srcH = ((s) < 4) ? (Ah1 + (size_t)gmc * 64 + (s) * 16)               \
                             : (Ah2 + (size_t)gmc * 64 + ((s) - 4) * 16);        \
        } else {                                                                 \
            srcH = Wh + (size_t)lr * 128 + (s) * 16;                             \
        }                                                                        \
        _Pragma("unroll")                                                        \
        for (int c = 0; c < 4; c++)                                              \
            CPA16(db + ((c * 4) ^ swl) * 4, srcH + c * 4, sz);                   \
        } while (0)

    CONV_LOAD(0, 0); CPC();
#pragma unroll 1
    for (int s = 0; s < 8; s++) {
        int buf = s & 1;
        if (s < 7) { CONV_LOAD(s + 1, buf ^ 1); CPC(); CPW1(); }
        else CPW0();
        __syncthreads();
        u32 Ab = smb + buf * 32768, Bb = Ab + 16384;
#pragma unroll
        for (int kk = 0; kk < 2; kk++) {
            u32 ah[2][4], bh[8][2];
#pragma unroll
            for (int mt = 0; mt < 2; mt++)
                LDSM4(ah[mt], Ab + offAh[mt][kk]);
#pragma unroll
            for (int p = 0; p < 4; p++) {
                u32 f[4];
                LDSM4(f, Bb + offBh[p][kk]);
                bh[2 * p][0] = f[0]; bh[2 * p][1] = f[1];
                bh[2 * p + 1][0] = f[2]; bh[2 * p + 1][1] = f[3];
            }
#pragma unroll
            for (int nt = 0; nt < 8; nt++)
#pragma unroll
                for (int mt = 0; mt < 2; mt++)
                    MMA16816(acc[mt][nt], ah[mt], bh[nt][0], bh[nt][1]);
        }
        __syncthreads();
    }
#undef CONV_LOAD

    int grp = lane >> 2, tig = lane & 3;
#pragma unroll
    for (int mt = 0; mt < 2; mt++)
#pragma unroll
        for (int nt = 0; nt < 8; nt++) {
            int col = ncol0 + nt * 8 + 2 * tig;
            float bx = __ldg(bias + col), by = __ldg(bias + col + 1);
            int r0 = m0 + mrow0 + mt * 16 + grp;
            if (r0 < N_NODES) {
                float v0 = fmaxf(acc[mt][nt][0] + bx, 0.0f);
                float v1 = fmaxf(acc[mt][nt][1] + by, 0.0f);
                *(float2*)&outp[(size_t)r0 * 128 + col] = make_float2(v0, v1);
                if (layer == 0)
                    g_h1h[(size_t)r0 * 64 + (col >> 1)] = pack2h(v0, v1);
            }
            int r1 = r0 + 8;
            if (r1 < N_NODES) {
                float v0 = fmaxf(acc[mt][nt][2] + bx, 0.0f);
                float v1 = fmaxf(acc[mt][nt][3] + by, 0.0f);
                *(float2*)&outp[(size_t)r1 * 128 + col] = make_float2(v0, v1);
                if (layer == 0)
                    g_h1h[(size_t)r1 * 64 + (col >> 1)] = pack2h(v0, v1);
            }
        }
}

/* ------------------------------------------------------------------ */
/* Phi materialization in fp16 (hi only)                               */
/* ------------------------------------------------------------------ */
__global__ void phi_kernel() {
    int t = blockIdx.x * blockDim.x + threadIdx.x;
    if (t >= N_NODES * 64) return;
    int n = t >> 6, ip = t & 63;
    float x0 = g_h2[(size_t)n * 128 + 2 * ip];
    float x1 = g_h2[(size_t)n * 128 + 2 * ip + 1];
    float v[18];
    bspline_basis(x0, v);      v[8]  = silu_f(x0);
    bspline_basis(x1, v + 9);  v[17] = silu_f(x1);
    u32* ph = g_phih + (size_t)n * K1W + ip * 9;
#pragma unroll
    for (int w = 0; w < 9; w++)
        ph[w] = pack2h(v[2 * w], v[2 * w + 1]);
}

/* ------------------------------------------------------------------ */
/* KAN1 GEMM (mma.sync fp16 1-PASS + cp.async + ldmatrix)              */
/* BM=128 BN=64 BK=32, 36 stages, 8 warps 4m x 2n (warp 32x32)         */
/* ------------------------------------------------------------------ */
__global__ __launch_bounds__(256, 1) void kan1_mma2_kernel() {
    extern __shared__ u32 sm[];
    int tid = threadIdx.x, lane = tid & 31, wid = tid >> 5;
    int m0 = blockIdx.x * 128;
    u32 smb = s2u(sm);

    int lr = tid & 127;
    bool isA = tid < 128;
    bool isB = (tid >= 128) && (tid < 192);
    int gmr = m0 + lr;
    int gmc = (gmr < N_NODES) ? gmr : 0;
    u32 sz = isA ? ((gmr < N_NODES) ? 16u : 0u) : 16u;
    u32 swl = (lr & 7) * 4;
    u32 dstb = smb + ((isA ? 0 : 4096) + lr * 32) * 4;

    int q = lane >> 3, rr = lane & 7;
    int mrow0 = (wid & 3) * 32, ncol0 = (wid >> 2) * 32;
    u32 offAh[2][2], offBh[2][2];
#pragma unroll
    for (int mt = 0; mt < 2; mt++)
#pragma unroll
        for (int kk = 0; kk < 2; kk++) {
            int row = mrow0 + mt * 16 + rr + (q & 1) * 8;
            u32 swz = (row & 7) * 4;
            offAh[mt][kk] = (row * 32 + ((kk * 8 + (q >> 1) * 4) ^ swz)) * 4;
        }
#pragma unroll
    for (int p = 0; p < 2; p++)
#pragma unroll
        for (int kk = 0; kk < 2; kk++) {
            int row = ncol0 + p * 16 + (q >> 1) * 8 + rr;
            u32 swz = (row & 7) * 4;
            offBh[p][kk] = (row * 32 + ((kk * 8 + (q & 1) * 4) ^ swz)) * 4;
        }

    float acc[2][4][4];
#pragma unroll
    for (int mt = 0; mt < 2; mt++)
#pragma unroll
        for (int nt = 0; nt < 4; nt++)
#pragma unroll
            for (int c = 0; c < 4; c++) acc[mt][nt][c] = 0.0f;

#define KAN_LOAD(s, buf) do {                                                    \
        u32 db = dstb + (buf) * 24576;                                           \
        if (isA) {                                                               \
            const u32* srcH = g_phih + (size_t)gmc * K1W + (s) * 16;             \
            _Pragma("unroll")                                                    \
            for (int c = 0; c < 4; c++)                                          \
                CPA16(db + ((c * 4) ^ swl) * 4, srcH + c * 4, sz);               \
        } else if (isB) {                                                        \
            const u32* srcH = g_wch + (size_t)lr * K1W + (s) * 16;               \
            _Pragma("unroll")                                                    \
            for (int c = 0; c < 4; c++)                                          \
                CPA16(db + ((c * 4) ^ swl) * 4, srcH + c * 4, sz);               \
        } } while (0)

    const int S = K1 / 32;  /* 36 */
    KAN_LOAD(0, 0); CPC();
#pragma unroll 1
    for (int s = 0; s < S; s++) {
        int buf = s & 1;
        if (s < S - 1) { KAN_LOAD(s + 1, buf ^ 1); CPC(); CPW1(); }
        else CPW0();
        __syncthreads();
        u32 Ab = smb + buf * 24576, Bb = Ab + 16384;
#pragma unroll
        for (int kk = 0; kk < 2; kk++) {
            u32 ah[2][4], bh[4][2];
#pragma unroll
            for (int mt = 0; mt < 2; mt++)
                LDSM4(ah[mt], Ab + offAh[mt][kk]);
#pragma unroll
            for (int p = 0; p < 2; p++) {
                u32 f[4];
                LDSM4(f, Bb + offBh[p][kk]);
                bh[2 * p][0] = f[0]; bh[2 * p][1] = f[1];
                bh[2 * p + 1][0] = f[2]; bh[2 * p + 1][1] = f[3];
            }
#pragma unroll
            for (int nt = 0; nt < 4; nt++)
#pragma unroll
                for (int mt = 0; mt < 2; mt++)
                    MMA16816(acc[mt][nt], ah[mt], bh[nt][0], bh[nt][1]);
        }
        __syncthreads();
    }
#undef KAN_LOAD

    int grp = lane >> 2, tig = lane & 3;
#pragma unroll
    for (int mt = 0; mt < 2; mt++)
#pragma unroll
        for (int nt = 0; nt < 4; nt++) {
            int col = ncol0 + nt * 8 + 2 * tig;
            int r0 = m0 + mrow0 + mt * 16 + grp;
            if (r0 < N_NODES)
                *(float2*)&g_hk[(size_t)r0 * 64 + col] =
                    make_float2(acc[mt][nt][0], acc[mt][nt][1]);
            int r1 = r0 + 8;
            if (r1 < N_NODES)
                *(float2*)&g_hk[(size_t)r1 * 64 + col] =
                    make_float2(acc[mt][nt][2], acc[mt][nt][3]);
        }
}

/* ------------------------------------------------------------------ */
/* KAN2: out[n][o] = sum_i basis(hk[n][i]) . w  (o = 0..1)             */
/* ------------------------------------------------------------------ */
__global__ __launch_bounds__(128) void kan2_kernel(const float* __restrict__ kb2,
                                                   const float* __restrict__ ks2,
                                                   float* __restrict__ out) {
    __shared__ float s_h[128 * 65];
    __shared__ float s_w[64 * 18];   /* [i][j(0..8)][o(0..1)] */
    int tid = threadIdx.x;
    for (int t = tid; t < 64 * 18; t += 128) {
        int i = t / 18, rem = t % 18, j = rem >> 1, o = rem & 1;
        s_w[t] = (j < 8) ? ks2[((size_t)o * 64 + i) * 8 + j] : kb2[o * 64 + i];
    }
    int n0 = blockIdx.x * 128;
    for (int t = tid; t < 128 * 64; t += 128) {
        int r = t >> 6, c = t & 63;
        int gn = n0 + r;
        s_h[r * 65 + c] = (gn < N_NODES) ? g_hk[(size_t)gn * 64 + c] : 0.0f;
    }
    __syncthreads();
    int gn = n0 + tid;
    if (gn >= N_NODES) return;
    float o0 = 0.0f, o1 = 0.0f;
    for (int i = 0; i < 64; i++) {
        float x = s_h[tid * 65 + i];
        float b[8];
        bspline_basis(x, b);
        float v8 = silu_f(x);
        const float* w = &s_w[i * 18];
#pragma unroll
        for (int j = 0; j < 8; j++) {
            o0 = fmaf(b[j], w[j * 2 + 0], o0);
            o1 = fmaf(b[j], w[j * 2 + 1], o1);
        }
        o0 = fmaf(v8, w[16], o0);
        o1 = fmaf(v8, w[17], o1);
    }
    out[(size_t)gn * 2 + 0] = o0;
    out[(size_t)gn * 2 + 1] = o1;
}

/* ------------------------------------------------------------------ */
extern "C" void kernel_launch(void* const* d_in, const int* in_sizes, int n_in,
                              void* d_out, int out_size) {
    const float* x   = (const float*)d_in[0];
    const int*   e   = (const int*)d_in[1];
    const float* W1l = (const float*)d_in[2];
    const float* b1  = (const float*)d_in[3];
    const float* W1r = (const float*)d_in[4];
    const float* W2l = (const float*)d_in[5];
    const float* b2  = (const float*)d_in[6];
    const float* W2r = (const float*)d_in[7];
    const float* kb1 = (const float*)d_in[8];
    const float* ks1 = (const float*)d_in[9];
    const float* kb2 = (const float*)d_in[10];
    const float* ks2 = (const float*)d_in[11];
    float* out = (float*)d_out;

    (void)in_sizes; (void)n_in; (void)out_size;

    const int CONV_SMEM = 65536;
    const int KAN_SMEM  = 49152;
    cudaFuncSetAttribute(conv_mma2_kernel, cudaFuncAttributeMaxDynamicSharedMemorySize, CONV_SMEM);
    cudaFuncSetAttribute(kan1_mma2_kernel, cudaFuncAttributeMaxDynamicSharedMemorySize, KAN_SMEM);

    const int EB = (N_EDGES + 255) / 256;
    const int MT = (N_NODES + 127) / 128;   /* 391 */

    initA_kernel<<<(N_NODES * 64 + 255) / 256, 256>>>(e, x, W1l, W1r, W2l, W2r, kb1, ks1);
    convert_kernel<<<EB, 256>>>(e);          /* + histogram */
    scan1_kernel<<<NBLK, 256>>>();
    scan2_kernel<<<1, 256>>>();
    scan3_kernel<<<NBLK, 256>>>();
    scatter_kernel<<<EB, 256>>>();

    /* layer 1 */
    agg_kernel<<<(N_NODES + 7) / 8, 256>>>(x, 0);
    conv_mma2_kernel<<<MT, 256, CONV_SMEM>>>(b1, 0);
    /* layer 2 */
    agg_kernel<<<(N_NODES + 7) / 8, 256>>>(x, 1);
    conv_mma2_kernel<<<MT, 256, CONV_SMEM>>>(b2, 1);
    /* KAN 1 */
    phi_kernel<<<(N_NODES * 64 + 255) / 256, 256>>>();
    kan1_mma2_kernel<<<MT, 256, KAN_SMEM>>>();
    /* KAN 2 */
    kan2_kernel<<<(N_NODES + 127) / 128, 128>>>(kb2, ks2, out);
}